// round 12
// baseline (speedup 1.0000x reference)
#include <cuda_runtime.h>
#include <cuda_fp16.h>
#include <cstdint>

// Problem dims (fixed per reference)
#define B_  2
#define T_  2048
#define C_  1024
#define H_  16
#define HD_ 64
#define C3_ 3072
#define M_ROWS (B_ * T_)   // 4096

// ---------------------------------------------------------------------------
// Scratch (allocation-free rule: device globals)   fp16 2-term scheme:
// A operands split hi+lo (exact to 2^-24), B operands single fp16 (err 2^-12)
// ---------------------------------------------------------------------------
__device__ __half g_qkvh[M_ROWS * C3_];   // qkv hi  [4096, 3072]
__device__ __half g_qkvl[M_ROWS * C3_];   // qkv lo  (only Q part consumed)
__device__ __half g_xh[M_ROWS * C_];
__device__ __half g_xl[M_ROWS * C_];
__device__ __half g_wah[C3_ * C_];        // W_attn^T fp16 [N=3072, K=1024]
__device__ __half g_wph[C_ * C_];         // W_proj^T fp16 [N=1024, K=1024]
__device__ __half g_ah[M_ROWS * C_];      // attention out hi
__device__ __half g_al[M_ROWS * C_];      // attention out lo

// ---------------------------------------------------------------------------
__device__ __forceinline__ uint32_t smem_u32(const void* p) {
    uint32_t a;
    asm("{ .reg .u64 t; cvta.to.shared.u64 t, %1; cvt.u32.u64 %0, t; }" : "=r"(a) : "l"(p));
    return a;
}
__device__ __forceinline__ void cp_async16(uint32_t saddr, const void* gaddr) {
    asm volatile("cp.async.cg.shared.global [%0], [%1], 16;" :: "r"(saddr), "l"(gaddr));
}
__device__ __forceinline__ void cp_commit() {
    asm volatile("cp.async.commit_group;" ::: "memory");
}
template <int N>
__device__ __forceinline__ void cp_wait() {
    asm volatile("cp.async.wait_group %0;" :: "n"(N) : "memory");
}
__device__ __forceinline__ void ldm_x4(uint32_t& r0, uint32_t& r1, uint32_t& r2, uint32_t& r3,
                                       uint32_t addr) {
    asm volatile("ldmatrix.sync.aligned.m8n8.x4.shared.b16 {%0,%1,%2,%3}, [%4];"
                 : "=r"(r0), "=r"(r1), "=r"(r2), "=r"(r3) : "r"(addr));
}
__device__ __forceinline__ void ldm_x4_t(uint32_t& r0, uint32_t& r1, uint32_t& r2, uint32_t& r3,
                                         uint32_t addr) {
    asm volatile("ldmatrix.sync.aligned.m8n8.x4.trans.shared.b16 {%0,%1,%2,%3}, [%4];"
                 : "=r"(r0), "=r"(r1), "=r"(r2), "=r"(r3) : "r"(addr));
}
__device__ __forceinline__ void mma_f16(float* c, uint32_t a0, uint32_t a1, uint32_t a2,
                                        uint32_t a3, uint32_t b0, uint32_t b1) {
    asm volatile(
        "mma.sync.aligned.m16n8k16.row.col.f32.f16.f16.f32 "
        "{%0,%1,%2,%3}, {%4,%5,%6,%7}, {%8,%9}, {%0,%1,%2,%3};"
        : "+f"(c[0]), "+f"(c[1]), "+f"(c[2]), "+f"(c[3])
        : "r"(a0), "r"(a1), "r"(a2), "r"(a3), "r"(b0), "r"(b1));
}
__device__ __forceinline__ uint32_t pack_f16(float lo_elem, float hi_elem) {
    __half2 t = __floats2half2_rn(lo_elem, hi_elem);
    return *(uint32_t*)&t;
}
__device__ __forceinline__ float f16_residual(float v) {
    return v - __half2float(__float2half(v));
}

// ---------------------------------------------------------------------------
// Split fp32 -> (hi, lo) fp16
// ---------------------------------------------------------------------------
__global__ __launch_bounds__(256) void split_kernel(
    const float* __restrict__ in, __half* __restrict__ hi,
    __half* __restrict__ lo, int n4)
{
    int i = blockIdx.x * blockDim.x + threadIdx.x;
    if (i >= n4) return;
    float4 v = ((const float4*)in)[i];
    float h0 = __half2float(__float2half(v.x));
    float h1 = __half2float(__float2half(v.y));
    float h2 = __half2float(__float2half(v.z));
    float h3 = __half2float(__float2half(v.w));
    uint32_t* ph = (uint32_t*)hi + i * 2;
    uint32_t* pl = (uint32_t*)lo + i * 2;
    ph[0] = pack_f16(v.x, v.y);  ph[1] = pack_f16(v.z, v.w);
    pl[0] = pack_f16(v.x - h0, v.y - h1);
    pl[1] = pack_f16(v.z - h2, v.w - h3);
}

// Transpose + fp16 round: in [K,N] fp32 -> hiT [N,K] fp16 (no residual)
__global__ __launch_bounds__(256) void transpose_f16_kernel(
    const float* __restrict__ in, __half* __restrict__ hiT, int K, int N)
{
    __shared__ float t[32][33];
    int n0 = blockIdx.x * 32, k0 = blockIdx.y * 32;
    int tx = threadIdx.x, ty = threadIdx.y;   // 32 x 8
#pragma unroll
    for (int i = 0; i < 32; i += 8)
        t[ty + i][tx] = in[(size_t)(k0 + ty + i) * N + n0 + tx];
    __syncthreads();
#pragma unroll
    for (int i = 0; i < 32; i += 8) {
        size_t o = (size_t)(n0 + ty + i) * K + k0 + tx;
        hiT[o] = __float2half(t[tx][ty + i]);
    }
}

// ---------------------------------------------------------------------------
// fp16 2-term GEMM via mma.sync:  C[M,N] = (Ah+Al)[M,K] @ Bh[N,K]^T
// 128x128 tile, BK=32, 256 threads, 3-stage cp.async pipeline (1 sync/iter).
// Warp tile 64x32 (warp grid 2x4): 32 MMA per 10 LDSM per k16-step.
// ---------------------------------------------------------------------------
#define GBM 128
#define GBN 128
#define GBK 32
#define LDT 40
#define TILE_B (128 * LDT * 2)
#define STAGE_B (3 * TILE_B)           // Ah, Al, Bh
#define NSTG 3
#define SMEM_GEMM (NSTG * STAGE_B)     // 92160

template <bool SPLIT>
__global__ __launch_bounds__(256, 2) void gemm_f16x2_kernel(
    const __half* __restrict__ Ah, const __half* __restrict__ Al,
    const __half* __restrict__ Bh,
    float* __restrict__ Cm, __half* __restrict__ Ch,
    __half* __restrict__ Cl, int M, int N, int K)
{
    extern __shared__ char smem[];
    const uint32_t sb = smem_u32(smem);
    const int tid = threadIdx.x;
    const int wid = tid >> 5, lane = tid & 31;
    const int warp_m = wid & 1;         // 0..1 -> 64 rows
    const int warp_n = wid >> 1;        // 0..3 -> 32 cols
    const int m0 = blockIdx.y * GBM;
    const int n0 = blockIdx.x * GBN;

    const __half* gsrc[3] = {Ah, Al, Bh};
    const int gbase[3] = {m0, m0, n0};

    float acc[4][4][4];                 // [mi 0..3][ni 0..3][quad]
#pragma unroll
    for (int i = 0; i < 4; i++)
#pragma unroll
        for (int j = 0; j < 4; j++)
#pragma unroll
            for (int q = 0; q < 4; q++) acc[i][j][q] = 0.f;

    auto load_stage = [&](int s, int ch) {
        const size_t koff = (size_t)ch * GBK;
        uint32_t sbase = sb + s * STAGE_B;
#pragma unroll
        for (int i = 0; i < 6; i++) {
            int chunk = tid + i * 256;          // 0..1535
            int t3 = chunk >> 9;                // tile 0..2
            int c2 = chunk & 511;
            int row = c2 >> 2, seg = c2 & 3;
            cp_async16(sbase + t3 * TILE_B + (uint32_t)(row * LDT + seg * 8) * 2,
                       gsrc[t3] + (size_t)(gbase[t3] + row) * K + koff + seg * 8);
        }
    };

    const int lrow = lane & 15;
    const int lcol = (lane >> 4) << 3;

    auto compute_stage = [&](int s) {
        uint32_t sbase = sb + s * STAGE_B;
        uint32_t sAh = sbase, sAl = sbase + TILE_B;
        uint32_t sBh = sbase + 2 * TILE_B;
#pragma unroll
        for (int ks = 0; ks < 2; ks++) {
            const int k0 = ks * 16;
            uint32_t ahf[4][4], alf[4][4];
#pragma unroll
            for (int mi = 0; mi < 4; mi++) {
                int r = warp_m * 64 + mi * 16 + lrow;
                uint32_t off = (uint32_t)(r * LDT + k0 + lcol) * 2;
                ldm_x4(ahf[mi][0], ahf[mi][1], ahf[mi][2], ahf[mi][3], sAh + off);
                ldm_x4(alf[mi][0], alf[mi][1], alf[mi][2], alf[mi][3], sAl + off);
            }
#pragma unroll
            for (int nt = 0; nt < 2; nt++) {
                int r = warp_n * 32 + nt * 16 + lrow;
                uint32_t off = (uint32_t)(r * LDT + k0 + lcol) * 2;
                uint32_t bh0, bh1, bh2, bh3;
                ldm_x4(bh0, bh1, bh2, bh3, sBh + off);
#pragma unroll
                for (int mi = 0; mi < 4; mi++) {
                    float* c0 = acc[mi][nt * 2];
                    float* c1 = acc[mi][nt * 2 + 1];
                    mma_f16(c0, ahf[mi][0], ahf[mi][1], ahf[mi][2], ahf[mi][3], bh0, bh2);
                    mma_f16(c1, ahf[mi][0], ahf[mi][1], ahf[mi][2], ahf[mi][3], bh1, bh3);
                    mma_f16(c0, alf[mi][0], alf[mi][1], alf[mi][2], alf[mi][3], bh0, bh2);
                    mma_f16(c1, alf[mi][0], alf[mi][1], alf[mi][2], alf[mi][3], bh1, bh3);
                }
            }
        }
    };

    const int nch = K / GBK;     // >= 2 always (K = 1024)
    load_stage(0, 0);
    cp_commit();
    load_stage(1, 1);
    cp_commit();
    for (int ch = 0; ch < nch; ch++) {
        cp_wait<1>();            // load ch complete (ch+1 may be in flight)
        __syncthreads();         // all warps see stage ch%3; prev compute done
        compute_stage(ch % NSTG);
        if (ch + 2 < nch) load_stage((ch + 2) % NSTG, ch + 2);
        cp_commit();
    }

    const int gid = lane >> 2;
    const int tig = lane & 3;
#pragma unroll
    for (int mi = 0; mi < 4; mi++) {
        int rbase = m0 + warp_m * 64 + mi * 16 + gid;
#pragma unroll
        for (int ni = 0; ni < 4; ni++) {
            int col = n0 + warp_n * 32 + ni * 8 + tig * 2;
            if (SPLIT) {
                float v0 = acc[mi][ni][0], v1 = acc[mi][ni][1];
                float v2 = acc[mi][ni][2], v3 = acc[mi][ni][3];
                *(uint32_t*)(Ch + (size_t)rbase * N + col) = pack_f16(v0, v1);
                *(uint32_t*)(Cl + (size_t)rbase * N + col) =
                    pack_f16(f16_residual(v0), f16_residual(v1));
                *(uint32_t*)(Ch + (size_t)(rbase + 8) * N + col) = pack_f16(v2, v3);
                *(uint32_t*)(Cl + (size_t)(rbase + 8) * N + col) =
                    pack_f16(f16_residual(v2), f16_residual(v3));
            } else {
                float* p0 = Cm + (size_t)rbase * N + col;
                float* p1 = Cm + (size_t)(rbase + 8) * N + col;
                p0[0] = acc[mi][ni][0]; p0[1] = acc[mi][ni][1];
                p1[0] = acc[mi][ni][2]; p1[1] = acc[mi][ni][3];
            }
        }
    }
}

// ---------------------------------------------------------------------------
// fp16 2-term flash attention, causal + column-0 emphasis.
// Q split hi/lo (persistent frags), K/V single fp16. P split in-register.
// 3-stage KV pipeline, 1 sync/iter. Grid (T/128, B*H), qt reversed.
// ---------------------------------------------------------------------------
#define AT_LD 72
#define AT_QT_B (128 * AT_LD * 2)          // 18432 per Q tile (hi or lo)
#define AT_KV_T (64 * AT_LD * 2)           // 9216 per KV tile
#define AT_STG  (2 * AT_KV_T)              // Kh, Vh
#define AT_NSTG 3
#define SMEM_ATTN (2 * AT_QT_B + AT_NSTG * AT_STG)   // 92160

__global__ __launch_bounds__(256, 1) void attn_mma_kernel(
    const __half* __restrict__ qkvh, const __half* __restrict__ qkvl,
    __half* __restrict__ ah, __half* __restrict__ al)
{
    extern __shared__ char smem[];
    const uint32_t sb = smem_u32(smem);
    const int tid = threadIdx.x;
    const int wid = tid >> 5, lane = tid & 31;
    const int qt = (int)gridDim.x - 1 - (int)blockIdx.x;   // heavy blocks first
    const int bh = blockIdx.y;
    const int b = bh >> 4, h = bh & 15;
    const int q0 = qt * 128;

    const uint32_t sQh = sb, sQl = sb + AT_QT_B;
    const uint32_t stg0 = sb + 2 * AT_QT_B;

    const int niters = 2 * qt + 2;     // >= 2 always

    // --- load Q (hi/lo), group 0 ---
#pragma unroll
    for (int i = 0; i < 8; i++) {
        int chunk = tid + i * 256;      // 0..2047
        int isLo = chunk >> 10;
        int c2 = chunk & 1023;
        int row = c2 >> 3, seg = c2 & 7;
        const __half* src = (isLo ? qkvl : qkvh) +
            (size_t)(b * T_ + q0 + row) * C3_ + h * HD_ + seg * 8;
        cp_async16((isLo ? sQl : sQh) + (uint32_t)(row * AT_LD + seg * 8) * 2, src);
    }
    cp_commit();

    auto load_kv = [&](int s, int it) {
        const int k0 = it * 64;
        uint32_t sbase = stg0 + s * AT_STG;
#pragma unroll
        for (int i = 0; i < 4; i++) {
            int chunk = tid + i * 256;      // 0..1023
            int t2 = chunk >> 9;            // 0=Kh 1=Vh
            int c2 = chunk & 511;
            int row = c2 >> 3, seg = c2 & 7;
            size_t coloff = (t2 == 0) ? (size_t)(C_ + h * HD_) : (size_t)(2 * C_ + h * HD_);
            cp_async16(sbase + t2 * AT_KV_T + (uint32_t)(row * AT_LD + seg * 8) * 2,
                       qkvh + (size_t)(b * T_ + k0 + row) * C3_ + coloff + seg * 8);
        }
    };
    load_kv(0, 0);
    cp_commit();
    load_kv(1, 1);
    cp_commit();

    const int lrow = lane & 15;
    const int lcol = (lane >> 4) << 3;
    const int gid = lane >> 2;
    const int tig = lane & 3;

    // Wait: Q + kv0 complete (kv1 may be pending)
    cp_wait<1>();
    __syncthreads();

    // --- Q fragments (persistent) ---
    uint32_t qh[4][4], ql[4][4];
#pragma unroll
    for (int kt = 0; kt < 4; kt++) {
        uint32_t off = (uint32_t)((wid * 16 + lrow) * AT_LD + kt * 16 + lcol) * 2;
        ldm_x4(qh[kt][0], qh[kt][1], qh[kt][2], qh[kt][3], sQh + off);
        ldm_x4(ql[kt][0], ql[kt][1], ql[kt][2], ql[kt][3], sQl + off);
    }

    float o[8][4];
#pragma unroll
    for (int i = 0; i < 8; i++)
#pragma unroll
        for (int j = 0; j < 4; j++) o[i][j] = 0.f;
    float m0r = -1e30f, m1r = -1e30f, l0r = 0.f, l1r = 0.f;

    for (int it = 0; it < niters; it++) {
        if (it > 0) {
            cp_wait<1>();        // kv(it) complete
            __syncthreads();
        }

        const uint32_t s_ = stg0 + (it % AT_NSTG) * AT_STG;
        const uint32_t sKh = s_, sVh = s_ + AT_KV_T;
        const int k0 = it * 64;
        const bool active = (q0 + wid * 16 + 15 >= k0);

        if (active) {
            // ---- S = Q @ K^T (2-term: Qh·K + Ql·K) ----
            float s[8][4];
#pragma unroll
            for (int i = 0; i < 8; i++)
#pragma unroll
                for (int j = 0; j < 4; j++) s[i][j] = 0.f;

#pragma unroll
            for (int kt = 0; kt < 4; kt++) {
#pragma unroll
                for (int np = 0; np < 4; np++) {
                    uint32_t boff = (uint32_t)((np * 16 + lrow) * AT_LD + kt * 16 + lcol) * 2;
                    uint32_t h0, h1, h2, h3;
                    ldm_x4(h0, h1, h2, h3, sKh + boff);
                    mma_f16(s[np * 2],     qh[kt][0], qh[kt][1], qh[kt][2], qh[kt][3], h0, h2);
                    mma_f16(s[np * 2 + 1], qh[kt][0], qh[kt][1], qh[kt][2], qh[kt][3], h1, h3);
                    mma_f16(s[np * 2],     ql[kt][0], ql[kt][1], ql[kt][2], ql[kt][3], h0, h2);
                    mma_f16(s[np * 2 + 1], ql[kt][0], ql[kt][1], ql[kt][2], ql[kt][3], h1, h3);
                }
            }

            // ---- scale + emphasis + causal mask ----
#pragma unroll
            for (int ni = 0; ni < 8; ni++)
#pragma unroll
                for (int e = 0; e < 4; e++) s[ni][e] *= 0.125f;
            if (it == 0 && tig == 0) { s[0][0] += 1.0f; s[0][2] += 1.0f; }
            const int grow0 = q0 + wid * 16 + gid;
            const int grow1 = grow0 + 8;
            if (k0 + 63 > q0 + wid * 16) {
#pragma unroll
                for (int ni = 0; ni < 8; ni++) {
                    int gc = k0 + ni * 8 + tig * 2;
                    if (gc > grow0)     s[ni][0] = -1e30f;
                    if (gc + 1 > grow0) s[ni][1] = -1e30f;
                    if (gc > grow1)     s[ni][2] = -1e30f;
                    if (gc + 1 > grow1) s[ni][3] = -1e30f;
                }
            }

            // ---- online softmax (rows grow0, grow1) ----
            float mx0 = s[0][0], mx1 = s[0][2];
#pragma unroll
            for (int ni = 0; ni < 8; ni++) {
                mx0 = fmaxf(mx0, fmaxf(s[ni][0], s[ni][1]));
                mx1 = fmaxf(mx1, fmaxf(s[ni][2], s[ni][3]));
            }
            mx0 = fmaxf(mx0, __shfl_xor_sync(0xffffffffu, mx0, 1));
            mx0 = fmaxf(mx0, __shfl_xor_sync(0xffffffffu, mx0, 2));
            mx1 = fmaxf(mx1, __shfl_xor_sync(0xffffffffu, mx1, 1));
            mx1 = fmaxf(mx1, __shfl_xor_sync(0xffffffffu, mx1, 2));
            float mn0 = fmaxf(m0r, mx0), mn1 = fmaxf(m1r, mx1);
            float a0 = __expf(m0r - mn0), a1 = __expf(m1r - mn1);
            m0r = mn0; m1r = mn1;
            float sum0 = 0.f, sum1 = 0.f;
#pragma unroll
            for (int ni = 0; ni < 8; ni++) {
                s[ni][0] = __expf(s[ni][0] - mn0);
                s[ni][1] = __expf(s[ni][1] - mn0);
                s[ni][2] = __expf(s[ni][2] - mn1);
                s[ni][3] = __expf(s[ni][3] - mn1);
                sum0 += s[ni][0] + s[ni][1];
                sum1 += s[ni][2] + s[ni][3];
            }
            sum0 += __shfl_xor_sync(0xffffffffu, sum0, 1);
            sum0 += __shfl_xor_sync(0xffffffffu, sum0, 2);
            sum1 += __shfl_xor_sync(0xffffffffu, sum1, 1);
            sum1 += __shfl_xor_sync(0xffffffffu, sum1, 2);
            l0r = l0r * a0 + sum0;
            l1r = l1r * a1 + sum1;

            // ---- rescale O ----
#pragma unroll
            for (int ni = 0; ni < 8; ni++) {
                o[ni][0] *= a0; o[ni][1] *= a0;
                o[ni][2] *= a1; o[ni][3] *= a1;
            }

            // ---- PV (2-term: (Ph+Pl)·V), V via ldmatrix.trans ----
#pragma unroll
            for (int kt = 0; kt < 4; kt++) {
                uint32_t ph[4], pl[4];
                {
                    float v0 = s[2 * kt][0], v1 = s[2 * kt][1];
                    float v2 = s[2 * kt][2], v3 = s[2 * kt][3];
                    float w0 = s[2 * kt + 1][0], w1 = s[2 * kt + 1][1];
                    float w2 = s[2 * kt + 1][2], w3 = s[2 * kt + 1][3];
                    ph[0] = pack_f16(v0, v1); ph[1] = pack_f16(v2, v3);
                    ph[2] = pack_f16(w0, w1); ph[3] = pack_f16(w2, w3);
                    pl[0] = pack_f16(f16_residual(v0), f16_residual(v1));
                    pl[1] = pack_f16(f16_residual(v2), f16_residual(v3));
                    pl[2] = pack_f16(f16_residual(w0), f16_residual(w1));
                    pl[3] = pack_f16(f16_residual(w2), f16_residual(w3));
                }
#pragma unroll
                for (int dp = 0; dp < 4; dp++) {
                    uint32_t voff = (uint32_t)((kt * 16 + lrow) * AT_LD + dp * 16 + lcol) * 2;
                    uint32_t h0, h1, h2, h3;
                    ldm_x4_t(h0, h1, h2, h3, sVh + voff);
                    mma_f16(o[dp * 2],     ph[0], ph[1], ph[2], ph[3], h0, h1);
                    mma_f16(o[dp * 2 + 1], ph[0], ph[1], ph[2], ph[3], h2, h3);
                    mma_f16(o[dp * 2],     pl[0], pl[1], pl[2], pl[3], h0, h1);
                    mma_f16(o[dp * 2 + 1], pl[0], pl[1], pl[2], pl[3], h2, h3);
                }
            }
        }

        if (it + 2 < niters) load_kv((it + 2) % AT_NSTG, it + 2);
        cp_commit();
    }

    // ---- epilogue: normalize, split hi/lo, store ----
    const float inv0 = 1.f / l0r, inv1 = 1.f / l1r;
    const int grow0 = q0 + wid * 16 + gid;
    const size_t r0o = (size_t)(b * T_ + grow0) * C_;
    const size_t r1o = (size_t)(b * T_ + grow0 + 8) * C_;
#pragma unroll
    for (int ni = 0; ni < 8; ni++) {
        int col = h * HD_ + ni * 8 + tig * 2;
        float v0 = o[ni][0] * inv0, v1 = o[ni][1] * inv0;
        float v2 = o[ni][2] * inv1, v3 = o[ni][3] * inv1;
        *(uint32_t*)(ah + r0o + col) = pack_f16(v0, v1);
        *(uint32_t*)(al + r0o + col) = pack_f16(f16_residual(v0), f16_residual(v1));
        *(uint32_t*)(ah + r1o + col) = pack_f16(v2, v3);
        *(uint32_t*)(al + r1o + col) = pack_f16(f16_residual(v2), f16_residual(v3));
    }
}

// ---------------------------------------------------------------------------
extern "C" void kernel_launch(void* const* d_in, const int* in_sizes, int n_in,
                              void* d_out, int out_size)
{
    const float* x  = (const float*)d_in[0];
    const float* Wa = (const float*)d_in[1];
    const float* Wp = (const float*)d_in[2];
    float* y = (float*)d_out;

    __half *qkvh, *qkvl, *xh, *xl, *wah, *wph, *ah, *al;
    cudaGetSymbolAddress((void**)&qkvh, g_qkvh);
    cudaGetSymbolAddress((void**)&qkvl, g_qkvl);
    cudaGetSymbolAddress((void**)&xh, g_xh);
    cudaGetSymbolAddress((void**)&xl, g_xl);
    cudaGetSymbolAddress((void**)&wah, g_wah);
    cudaGetSymbolAddress((void**)&wph, g_wph);
    cudaGetSymbolAddress((void**)&ah, g_ah);
    cudaGetSymbolAddress((void**)&al, g_al);

    cudaFuncSetAttribute(gemm_f16x2_kernel<true>,
                         cudaFuncAttributeMaxDynamicSharedMemorySize, SMEM_GEMM);
    cudaFuncSetAttribute(gemm_f16x2_kernel<false>,
                         cudaFuncAttributeMaxDynamicSharedMemorySize, SMEM_GEMM);
    cudaFuncSetAttribute(attn_mma_kernel,
                         cudaFuncAttributeMaxDynamicSharedMemorySize, SMEM_ATTN);

    // 1) splits / weight transposes
    {
        int n4 = M_ROWS * C_ / 4;
        split_kernel<<<(n4 + 255) / 256, 256>>>(x, xh, xl, n4);
        dim3 grid_a(C3_ / 32, C_ / 32);
        transpose_f16_kernel<<<grid_a, dim3(32, 8)>>>(Wa, wah, C_, C3_);
        dim3 grid_p(C_ / 32, C_ / 32);
        transpose_f16_kernel<<<grid_p, dim3(32, 8)>>>(Wp, wph, C_, C_);
    }

    // 2) qkv = x @ W_attn -> fp16 hi/lo directly
    {
        dim3 grid(C3_ / GBN, M_ROWS / GBM);
        gemm_f16x2_kernel<true><<<grid, 256, SMEM_GEMM>>>(
            xh, xl, wah, nullptr, qkvh, qkvl, M_ROWS, C3_, C_);
    }

    // 3) flash attention -> fp16 hi/lo
    {
        dim3 grid(T_ / 128, B_ * H_);
        attn_mma_kernel<<<grid, 256, SMEM_ATTN>>>(qkvh, qkvl, ah, al);
    }

    // 4) y = att @ W_proj (fp32 out)
    {
        dim3 grid(C_ / GBN, M_ROWS / GBM);
        gemm_f16x2_kernel<false><<<grid, 256, SMEM_GEMM>>>(
            ah, al, wph, y, nullptr, nullptr, M_ROWS, C_, C_);
    }
}

// round 13
// speedup vs baseline: 1.0284x; 1.0284x over previous
#include <cuda_runtime.h>
#include <cuda_fp16.h>
#include <cstdint>

// Problem dims (fixed per reference)
#define B_  2
#define T_  2048
#define C_  1024
#define H_  16
#define HD_ 64
#define C3_ 3072
#define M_ROWS (B_ * T_)   // 4096

// ---------------------------------------------------------------------------
// Scratch (allocation-free rule: device globals)   fp16 2-term scheme:
// A operands split hi+lo (exact to 2^-24), B operands single fp16 (err 2^-12)
// ---------------------------------------------------------------------------
__device__ __half g_qkvh[M_ROWS * C3_];   // qkv hi  [4096, 3072]
__device__ __half g_qkvl[M_ROWS * C3_];   // qkv lo  (only Q part consumed)
__device__ __half g_xh[M_ROWS * C_];
__device__ __half g_xl[M_ROWS * C_];
__device__ __half g_wah[C3_ * C_];        // W_attn^T fp16 [N=3072, K=1024]
__device__ __half g_wph[C_ * C_];         // W_proj^T fp16 [N=1024, K=1024]
__device__ __half g_ah[M_ROWS * C_];      // attention out hi
__device__ __half g_al[M_ROWS * C_];      // attention out lo

// ---------------------------------------------------------------------------
__device__ __forceinline__ uint32_t smem_u32(const void* p) {
    uint32_t a;
    asm("{ .reg .u64 t; cvta.to.shared.u64 t, %1; cvt.u32.u64 %0, t; }" : "=r"(a) : "l"(p));
    return a;
}
__device__ __forceinline__ void cp_async16(uint32_t saddr, const void* gaddr) {
    asm volatile("cp.async.cg.shared.global [%0], [%1], 16;" :: "r"(saddr), "l"(gaddr));
}
__device__ __forceinline__ void cp_commit() {
    asm volatile("cp.async.commit_group;" ::: "memory");
}
template <int N>
__device__ __forceinline__ void cp_wait() {
    asm volatile("cp.async.wait_group %0;" :: "n"(N) : "memory");
}
__device__ __forceinline__ void ldm_x4(uint32_t& r0, uint32_t& r1, uint32_t& r2, uint32_t& r3,
                                       uint32_t addr) {
    asm volatile("ldmatrix.sync.aligned.m8n8.x4.shared.b16 {%0,%1,%2,%3}, [%4];"
                 : "=r"(r0), "=r"(r1), "=r"(r2), "=r"(r3) : "r"(addr));
}
__device__ __forceinline__ void ldm_x4_t(uint32_t& r0, uint32_t& r1, uint32_t& r2, uint32_t& r3,
                                         uint32_t addr) {
    asm volatile("ldmatrix.sync.aligned.m8n8.x4.trans.shared.b16 {%0,%1,%2,%3}, [%4];"
                 : "=r"(r0), "=r"(r1), "=r"(r2), "=r"(r3) : "r"(addr));
}
__device__ __forceinline__ void mma_f16(float* c, uint32_t a0, uint32_t a1, uint32_t a2,
                                        uint32_t a3, uint32_t b0, uint32_t b1) {
    asm volatile(
        "mma.sync.aligned.m16n8k16.row.col.f32.f16.f16.f32 "
        "{%0,%1,%2,%3}, {%4,%5,%6,%7}, {%8,%9}, {%0,%1,%2,%3};"
        : "+f"(c[0]), "+f"(c[1]), "+f"(c[2]), "+f"(c[3])
        : "r"(a0), "r"(a1), "r"(a2), "r"(a3), "r"(b0), "r"(b1));
}
__device__ __forceinline__ uint32_t pack_f16(float lo_elem, float hi_elem) {
    __half2 t = __floats2half2_rn(lo_elem, hi_elem);
    return *(uint32_t*)&t;
}
__device__ __forceinline__ float f16_residual(float v) {
    return v - __half2float(__float2half(v));
}

// ---------------------------------------------------------------------------
// Split fp32 -> (hi, lo) fp16
// ---------------------------------------------------------------------------
__global__ __launch_bounds__(256) void split_kernel(
    const float* __restrict__ in, __half* __restrict__ hi,
    __half* __restrict__ lo, int n4)
{
    int i = blockIdx.x * blockDim.x + threadIdx.x;
    if (i >= n4) return;
    float4 v = ((const float4*)in)[i];
    float h0 = __half2float(__float2half(v.x));
    float h1 = __half2float(__float2half(v.y));
    float h2 = __half2float(__float2half(v.z));
    float h3 = __half2float(__float2half(v.w));
    uint32_t* ph = (uint32_t*)hi + i * 2;
    uint32_t* pl = (uint32_t*)lo + i * 2;
    ph[0] = pack_f16(v.x, v.y);  ph[1] = pack_f16(v.z, v.w);
    pl[0] = pack_f16(v.x - h0, v.y - h1);
    pl[1] = pack_f16(v.z - h2, v.w - h3);
}

// Transpose + fp16 round: in [K,N] fp32 -> hiT [N,K] fp16 (no residual)
__global__ __launch_bounds__(256) void transpose_f16_kernel(
    const float* __restrict__ in, __half* __restrict__ hiT, int K, int N)
{
    __shared__ float t[32][33];
    int n0 = blockIdx.x * 32, k0 = blockIdx.y * 32;
    int tx = threadIdx.x, ty = threadIdx.y;   // 32 x 8
#pragma unroll
    for (int i = 0; i < 32; i += 8)
        t[ty + i][tx] = in[(size_t)(k0 + ty + i) * N + n0 + tx];
    __syncthreads();
#pragma unroll
    for (int i = 0; i < 32; i += 8) {
        size_t o = (size_t)(n0 + ty + i) * K + k0 + tx;
        hiT[o] = __float2half(t[tx][ty + i]);
    }
}

// ---------------------------------------------------------------------------
// fp16 2-term GEMM via mma.sync:  C[M,N] = (Ah+Al)[M,K] @ Bh[N,K]^T
// 128x128 tile, BK=32, 256 threads, 3-stage cp.async pipeline.
// Warp tile 32x64 (grid 4x2). Two-pass MMA scheduling: all 16 hi-term MMAs
// (distinct accumulators), then all 16 lo-term MMAs -> no scoreboard stalls.
// ---------------------------------------------------------------------------
#define GBM 128
#define GBN 128
#define GBK 32
#define LDT 40
#define TILE_B (128 * LDT * 2)
#define STAGE_B (3 * TILE_B)           // Ah, Al, Bh
#define NSTG 3
#define SMEM_GEMM (NSTG * STAGE_B)     // 92160

template <bool SPLIT>
__global__ __launch_bounds__(256, 2) void gemm_f16x2_kernel(
    const __half* __restrict__ Ah, const __half* __restrict__ Al,
    const __half* __restrict__ Bh,
    float* __restrict__ Cm, __half* __restrict__ Ch,
    __half* __restrict__ Cl, int M, int N, int K)
{
    extern __shared__ char smem[];
    const uint32_t sb = smem_u32(smem);
    const int tid = threadIdx.x;
    const int wid = tid >> 5, lane = tid & 31;
    const int warp_m = wid >> 1;        // 0..3 -> 32 rows
    const int warp_n = wid & 1;         // 0..1 -> 64 cols
    const int m0 = blockIdx.y * GBM;
    const int n0 = blockIdx.x * GBN;

    const __half* gsrc[3] = {Ah, Al, Bh};
    const int gbase[3] = {m0, m0, n0};

    float acc[2][8][4];
#pragma unroll
    for (int i = 0; i < 2; i++)
#pragma unroll
        for (int j = 0; j < 8; j++)
#pragma unroll
            for (int q = 0; q < 4; q++) acc[i][j][q] = 0.f;

    auto load_stage = [&](int s, int ch) {
        const size_t koff = (size_t)ch * GBK;
        uint32_t sbase = sb + s * STAGE_B;
#pragma unroll
        for (int i = 0; i < 6; i++) {
            int chunk = tid + i * 256;          // 0..1535
            int t3 = chunk >> 9;                // tile 0..2
            int c2 = chunk & 511;
            int row = c2 >> 2, seg = c2 & 3;
            cp_async16(sbase + t3 * TILE_B + (uint32_t)(row * LDT + seg * 8) * 2,
                       gsrc[t3] + (size_t)(gbase[t3] + row) * K + koff + seg * 8);
        }
    };

    const int lrow = lane & 15;
    const int lcol = (lane >> 4) << 3;

    auto compute_stage = [&](int s) {
        uint32_t sbase = sb + s * STAGE_B;
        uint32_t sAh = sbase, sAl = sbase + TILE_B;
        uint32_t sBh = sbase + 2 * TILE_B;
#pragma unroll
        for (int ks = 0; ks < 2; ks++) {
            const int k0 = ks * 16;
            uint32_t ahf[2][4], alf[2][4];
#pragma unroll
            for (int mi = 0; mi < 2; mi++) {
                int r = warp_m * 32 + mi * 16 + lrow;
                uint32_t off = (uint32_t)(r * LDT + k0 + lcol) * 2;
                ldm_x4(ahf[mi][0], ahf[mi][1], ahf[mi][2], ahf[mi][3], sAh + off);
                ldm_x4(alf[mi][0], alf[mi][1], alf[mi][2], alf[mi][3], sAl + off);
            }
            uint32_t bf[4][4];
#pragma unroll
            for (int nt = 0; nt < 4; nt++) {
                int r = warp_n * 64 + nt * 16 + lrow;
                uint32_t off = (uint32_t)(r * LDT + k0 + lcol) * 2;
                ldm_x4(bf[nt][0], bf[nt][1], bf[nt][2], bf[nt][3], sBh + off);
            }
            // hi pass: 16 MMAs, all distinct accumulators (no dependency stalls)
#pragma unroll
            for (int nt = 0; nt < 4; nt++)
#pragma unroll
                for (int mi = 0; mi < 2; mi++) {
                    mma_f16(acc[mi][nt * 2],     ahf[mi][0], ahf[mi][1], ahf[mi][2], ahf[mi][3],
                            bf[nt][0], bf[nt][2]);
                    mma_f16(acc[mi][nt * 2 + 1], ahf[mi][0], ahf[mi][1], ahf[mi][2], ahf[mi][3],
                            bf[nt][1], bf[nt][3]);
                }
            // lo pass: same accumulators at reuse distance 16
#pragma unroll
            for (int nt = 0; nt < 4; nt++)
#pragma unroll
                for (int mi = 0; mi < 2; mi++) {
                    mma_f16(acc[mi][nt * 2],     alf[mi][0], alf[mi][1], alf[mi][2], alf[mi][3],
                            bf[nt][0], bf[nt][2]);
                    mma_f16(acc[mi][nt * 2 + 1], alf[mi][0], alf[mi][1], alf[mi][2], alf[mi][3],
                            bf[nt][1], bf[nt][3]);
                }
        }
    };

    const int nch = K / GBK;     // >= 2 always (K = 1024)
    load_stage(0, 0);
    cp_commit();
    load_stage(1, 1);
    cp_commit();
    for (int ch = 0; ch < nch; ch++) {
        cp_wait<1>();            // load ch complete (ch+1 may be in flight)
        __syncthreads();         // all warps see stage ch%3; prev compute done
        compute_stage(ch % NSTG);
        if (ch + 2 < nch) load_stage((ch + 2) % NSTG, ch + 2);
        cp_commit();
    }

    const int gid = lane >> 2;
    const int tig = lane & 3;
#pragma unroll
    for (int mi = 0; mi < 2; mi++) {
        int rbase = m0 + warp_m * 32 + mi * 16 + gid;
#pragma unroll
        for (int ni = 0; ni < 8; ni++) {
            int col = n0 + warp_n * 64 + ni * 8 + tig * 2;
            if (SPLIT) {
                float v0 = acc[mi][ni][0], v1 = acc[mi][ni][1];
                float v2 = acc[mi][ni][2], v3 = acc[mi][ni][3];
                *(uint32_t*)(Ch + (size_t)rbase * N + col) = pack_f16(v0, v1);
                *(uint32_t*)(Cl + (size_t)rbase * N + col) =
                    pack_f16(f16_residual(v0), f16_residual(v1));
                *(uint32_t*)(Ch + (size_t)(rbase + 8) * N + col) = pack_f16(v2, v3);
                *(uint32_t*)(Cl + (size_t)(rbase + 8) * N + col) =
                    pack_f16(f16_residual(v2), f16_residual(v3));
            } else {
                float* p0 = Cm + (size_t)rbase * N + col;
                float* p1 = Cm + (size_t)(rbase + 8) * N + col;
                p0[0] = acc[mi][ni][0]; p0[1] = acc[mi][ni][1];
                p1[0] = acc[mi][ni][2]; p1[1] = acc[mi][ni][3];
            }
        }
    }
}

// ---------------------------------------------------------------------------
// fp16 2-term flash attention, causal + column-0 emphasis.
// Q split hi/lo (persistent frags), K/V single fp16. P split in-register.
// 3-stage KV pipeline. Two-pass MMA scheduling in S and PV loops.
// Grid (T/128, B*H), 256 threads, qt reversed.
// ---------------------------------------------------------------------------
#define AT_LD 72
#define AT_QT_B (128 * AT_LD * 2)          // 18432 per Q tile (hi or lo)
#define AT_KV_T (64 * AT_LD * 2)           // 9216 per KV tile
#define AT_STG  (2 * AT_KV_T)              // Kh, Vh
#define AT_NSTG 3
#define SMEM_ATTN (2 * AT_QT_B + AT_NSTG * AT_STG)   // 92160

__global__ __launch_bounds__(256, 1) void attn_mma_kernel(
    const __half* __restrict__ qkvh, const __half* __restrict__ qkvl,
    __half* __restrict__ ah, __half* __restrict__ al)
{
    extern __shared__ char smem[];
    const uint32_t sb = smem_u32(smem);
    const int tid = threadIdx.x;
    const int wid = tid >> 5, lane = tid & 31;
    const int qt = (int)gridDim.x - 1 - (int)blockIdx.x;   // heavy blocks first
    const int bh = blockIdx.y;
    const int b = bh >> 4, h = bh & 15;
    const int q0 = qt * 128;

    const uint32_t sQh = sb, sQl = sb + AT_QT_B;
    const uint32_t stg0 = sb + 2 * AT_QT_B;

    const int niters = 2 * qt + 2;     // >= 2 always

    // --- load Q (hi/lo), group 0 ---
#pragma unroll
    for (int i = 0; i < 8; i++) {
        int chunk = tid + i * 256;      // 0..2047
        int isLo = chunk >> 10;
        int c2 = chunk & 1023;
        int row = c2 >> 3, seg = c2 & 7;
        const __half* src = (isLo ? qkvl : qkvh) +
            (size_t)(b * T_ + q0 + row) * C3_ + h * HD_ + seg * 8;
        cp_async16((isLo ? sQl : sQh) + (uint32_t)(row * AT_LD + seg * 8) * 2, src);
    }
    cp_commit();

    auto load_kv = [&](int s, int it) {
        const int k0 = it * 64;
        uint32_t sbase = stg0 + s * AT_STG;
#pragma unroll
        for (int i = 0; i < 4; i++) {
            int chunk = tid + i * 256;      // 0..1023
            int t2 = chunk >> 9;            // 0=Kh 1=Vh
            int c2 = chunk & 511;
            int row = c2 >> 3, seg = c2 & 7;
            size_t coloff = (t2 == 0) ? (size_t)(C_ + h * HD_) : (size_t)(2 * C_ + h * HD_);
            cp_async16(sbase + t2 * AT_KV_T + (uint32_t)(row * AT_LD + seg * 8) * 2,
                       qkvh + (size_t)(b * T_ + k0 + row) * C3_ + coloff + seg * 8);
        }
    };
    load_kv(0, 0);
    cp_commit();
    load_kv(1, 1);
    cp_commit();

    const int lrow = lane & 15;
    const int lcol = (lane >> 4) << 3;
    const int gid = lane >> 2;
    const int tig = lane & 3;

    // Wait: Q + kv0 complete (kv1 may be pending)
    cp_wait<1>();
    __syncthreads();

    // --- Q fragments (persistent) ---
    uint32_t qh[4][4], ql[4][4];
#pragma unroll
    for (int kt = 0; kt < 4; kt++) {
        uint32_t off = (uint32_t)((wid * 16 + lrow) * AT_LD + kt * 16 + lcol) * 2;
        ldm_x4(qh[kt][0], qh[kt][1], qh[kt][2], qh[kt][3], sQh + off);
        ldm_x4(ql[kt][0], ql[kt][1], ql[kt][2], ql[kt][3], sQl + off);
    }

    float o[8][4];
#pragma unroll
    for (int i = 0; i < 8; i++)
#pragma unroll
        for (int j = 0; j < 4; j++) o[i][j] = 0.f;
    float m0r = -1e30f, m1r = -1e30f, l0r = 0.f, l1r = 0.f;

    for (int it = 0; it < niters; it++) {
        if (it > 0) {
            cp_wait<1>();        // kv(it) complete
            __syncthreads();
        }

        const uint32_t s_ = stg0 + (it % AT_NSTG) * AT_STG;
        const uint32_t sKh = s_, sVh = s_ + AT_KV_T;
        const int k0 = it * 64;
        const bool active = (q0 + wid * 16 + 15 >= k0);

        if (active) {
            // ---- S = Q @ K^T (2-term), two-pass per kt ----
            float s[8][4];
#pragma unroll
            for (int i = 0; i < 8; i++)
#pragma unroll
                for (int j = 0; j < 4; j++) s[i][j] = 0.f;

#pragma unroll
            for (int kt = 0; kt < 4; kt++) {
                uint32_t kf[4][4];
#pragma unroll
                for (int np = 0; np < 4; np++) {
                    uint32_t boff = (uint32_t)((np * 16 + lrow) * AT_LD + kt * 16 + lcol) * 2;
                    ldm_x4(kf[np][0], kf[np][1], kf[np][2], kf[np][3], sKh + boff);
                }
                // hi pass: 8 distinct accumulators
#pragma unroll
                for (int np = 0; np < 4; np++) {
                    mma_f16(s[np * 2],     qh[kt][0], qh[kt][1], qh[kt][2], qh[kt][3],
                            kf[np][0], kf[np][2]);
                    mma_f16(s[np * 2 + 1], qh[kt][0], qh[kt][1], qh[kt][2], qh[kt][3],
                            kf[np][1], kf[np][3]);
                }
                // lo pass
#pragma unroll
                for (int np = 0; np < 4; np++) {
                    mma_f16(s[np * 2],     ql[kt][0], ql[kt][1], ql[kt][2], ql[kt][3],
                            kf[np][0], kf[np][2]);
                    mma_f16(s[np * 2 + 1], ql[kt][0], ql[kt][1], ql[kt][2], ql[kt][3],
                            kf[np][1], kf[np][3]);
                }
            }

            // ---- scale + emphasis + causal mask ----
#pragma unroll
            for (int ni = 0; ni < 8; ni++)
#pragma unroll
                for (int e = 0; e < 4; e++) s[ni][e] *= 0.125f;
            if (it == 0 && tig == 0) { s[0][0] += 1.0f; s[0][2] += 1.0f; }
            const int grow0 = q0 + wid * 16 + gid;
            const int grow1 = grow0 + 8;
            if (k0 + 63 > q0 + wid * 16) {
#pragma unroll
                for (int ni = 0; ni < 8; ni++) {
                    int gc = k0 + ni * 8 + tig * 2;
                    if (gc > grow0)     s[ni][0] = -1e30f;
                    if (gc + 1 > grow0) s[ni][1] = -1e30f;
                    if (gc > grow1)     s[ni][2] = -1e30f;
                    if (gc + 1 > grow1) s[ni][3] = -1e30f;
                }
            }

            // ---- online softmax (rows grow0, grow1) ----
            float mx0 = s[0][0], mx1 = s[0][2];
#pragma unroll
            for (int ni = 0; ni < 8; ni++) {
                mx0 = fmaxf(mx0, fmaxf(s[ni][0], s[ni][1]));
                mx1 = fmaxf(mx1, fmaxf(s[ni][2], s[ni][3]));
            }
            mx0 = fmaxf(mx0, __shfl_xor_sync(0xffffffffu, mx0, 1));
            mx0 = fmaxf(mx0, __shfl_xor_sync(0xffffffffu, mx0, 2));
            mx1 = fmaxf(mx1, __shfl_xor_sync(0xffffffffu, mx1, 1));
            mx1 = fmaxf(mx1, __shfl_xor_sync(0xffffffffu, mx1, 2));
            float mn0 = fmaxf(m0r, mx0), mn1 = fmaxf(m1r, mx1);
            float a0 = __expf(m0r - mn0), a1 = __expf(m1r - mn1);
            m0r = mn0; m1r = mn1;
            float sum0 = 0.f, sum1 = 0.f;
#pragma unroll
            for (int ni = 0; ni < 8; ni++) {
                s[ni][0] = __expf(s[ni][0] - mn0);
                s[ni][1] = __expf(s[ni][1] - mn0);
                s[ni][2] = __expf(s[ni][2] - mn1);
                s[ni][3] = __expf(s[ni][3] - mn1);
                sum0 += s[ni][0] + s[ni][1];
                sum1 += s[ni][2] + s[ni][3];
            }
            sum0 += __shfl_xor_sync(0xffffffffu, sum0, 1);
            sum0 += __shfl_xor_sync(0xffffffffu, sum0, 2);
            sum1 += __shfl_xor_sync(0xffffffffu, sum1, 1);
            sum1 += __shfl_xor_sync(0xffffffffu, sum1, 2);
            l0r = l0r * a0 + sum0;
            l1r = l1r * a1 + sum1;

            // ---- rescale O ----
#pragma unroll
            for (int ni = 0; ni < 8; ni++) {
                o[ni][0] *= a0; o[ni][1] *= a0;
                o[ni][2] *= a1; o[ni][3] *= a1;
            }

            // ---- PV (2-term), two-pass per kt; V via ldmatrix.trans ----
#pragma unroll
            for (int kt = 0; kt < 4; kt++) {
                uint32_t ph[4], pl[4];
                {
                    float v0 = s[2 * kt][0], v1 = s[2 * kt][1];
                    float v2 = s[2 * kt][2], v3 = s[2 * kt][3];
                    float w0 = s[2 * kt + 1][0], w1 = s[2 * kt + 1][1];
                    float w2 = s[2 * kt + 1][2], w3 = s[2 * kt + 1][3];
                    ph[0] = pack_f16(v0, v1); ph[1] = pack_f16(v2, v3);
                    ph[2] = pack_f16(w0, w1); ph[3] = pack_f16(w2, w3);
                    pl[0] = pack_f16(f16_residual(v0), f16_residual(v1));
                    pl[1] = pack_f16(f16_residual(v2), f16_residual(v3));
                    pl[2] = pack_f16(f16_residual(w0), f16_residual(w1));
                    pl[3] = pack_f16(f16_residual(w2), f16_residual(w3));
                }
                uint32_t vf[4][4];
#pragma unroll
                for (int dp = 0; dp < 4; dp++) {
                    uint32_t voff = (uint32_t)((kt * 16 + lrow) * AT_LD + dp * 16 + lcol) * 2;
                    ldm_x4_t(vf[dp][0], vf[dp][1], vf[dp][2], vf[dp][3], sVh + voff);
                }
                // ph pass: 8 distinct o-accumulators
#pragma unroll
                for (int dp = 0; dp < 4; dp++) {
                    mma_f16(o[dp * 2],     ph[0], ph[1], ph[2], ph[3], vf[dp][0], vf[dp][1]);
                    mma_f16(o[dp * 2 + 1], ph[0], ph[1], ph[2], ph[3], vf[dp][2], vf[dp][3]);
                }
                // pl pass
#pragma unroll
                for (int dp = 0; dp < 4; dp++) {
                    mma_f16(o[dp * 2],     pl[0], pl[1], pl[2], pl[3], vf[dp][0], vf[dp][1]);
                    mma_f16(o[dp * 2 + 1], pl[0], pl[1], pl[2], pl[3], vf[dp][2], vf[dp][3]);
                }
            }
        }

        if (it + 2 < niters) load_kv((it + 2) % AT_NSTG, it + 2);
        cp_commit();
    }

    // ---- epilogue: normalize, split hi/lo, store ----
    const float inv0 = 1.f / l0r, inv1 = 1.f / l1r;
    const int grow0 = q0 + wid * 16 + gid;
    const size_t r0o = (size_t)(b * T_ + grow0) * C_;
    const size_t r1o = (size_t)(b * T_ + grow0 + 8) * C_;
#pragma unroll
    for (int ni = 0; ni < 8; ni++) {
        int col = h * HD_ + ni * 8 + tig * 2;
        float v0 = o[ni][0] * inv0, v1 = o[ni][1] * inv0;
        float v2 = o[ni][2] * inv1, v3 = o[ni][3] * inv1;
        *(uint32_t*)(ah + r0o + col) = pack_f16(v0, v1);
        *(uint32_t*)(al + r0o + col) = pack_f16(f16_residual(v0), f16_residual(v1));
        *(uint32_t*)(ah + r1o + col) = pack_f16(v2, v3);
        *(uint32_t*)(al + r1o + col) = pack_f16(f16_residual(v2), f16_residual(v3));
    }
}

// ---------------------------------------------------------------------------
extern "C" void kernel_launch(void* const* d_in, const int* in_sizes, int n_in,
                              void* d_out, int out_size)
{
    const float* x  = (const float*)d_in[0];
    const float* Wa = (const float*)d_in[1];
    const float* Wp = (const float*)d_in[2];
    float* y = (float*)d_out;

    __half *qkvh, *qkvl, *xh, *xl, *wah, *wph, *ah, *al;
    cudaGetSymbolAddress((void**)&qkvh, g_qkvh);
    cudaGetSymbolAddress((void**)&qkvl, g_qkvl);
    cudaGetSymbolAddress((void**)&xh, g_xh);
    cudaGetSymbolAddress((void**)&xl, g_xl);
    cudaGetSymbolAddress((void**)&wah, g_wah);
    cudaGetSymbolAddress((void**)&wph, g_wph);
    cudaGetSymbolAddress((void**)&ah, g_ah);
    cudaGetSymbolAddress((void**)&al, g_al);

    cudaFuncSetAttribute(gemm_f16x2_kernel<true>,
                         cudaFuncAttributeMaxDynamicSharedMemorySize, SMEM_GEMM);
    cudaFuncSetAttribute(gemm_f16x2_kernel<false>,
                         cudaFuncAttributeMaxDynamicSharedMemorySize, SMEM_GEMM);
    cudaFuncSetAttribute(attn_mma_kernel,
                         cudaFuncAttributeMaxDynamicSharedMemorySize, SMEM_ATTN);

    // 1) splits / weight transposes
    {
        int n4 = M_ROWS * C_ / 4;
        split_kernel<<<(n4 + 255) / 256, 256>>>(x, xh, xl, n4);
        dim3 grid_a(C3_ / 32, C_ / 32);
        transpose_f16_kernel<<<grid_a, dim3(32, 8)>>>(Wa, wah, C_, C3_);
        dim3 grid_p(C_ / 32, C_ / 32);
        transpose_f16_kernel<<<grid_p, dim3(32, 8)>>>(Wp, wph, C_, C_);
    }

    // 2) qkv = x @ W_attn -> fp16 hi/lo directly
    {
        dim3 grid(C3_ / GBN, M_ROWS / GBM);
        gemm_f16x2_kernel<true><<<grid, 256, SMEM_GEMM>>>(
            xh, xl, wah, nullptr, qkvh, qkvl, M_ROWS, C3_, C_);
    }

    // 3) flash attention -> fp16 hi/lo
    {
        dim3 grid(T_ / 128, B_ * H_);
        attn_mma_kernel<<<grid, 256, SMEM_ATTN>>>(qkvh, qkvl, ah, al);
    }

    // 4) y = att @ W_proj (fp32 out)
    {
        dim3 grid(C_ / GBN, M_ROWS / GBM);
        gemm_f16x2_kernel<false><<<grid, 256, SMEM_GEMM>>>(
            ah, al, wph, y, nullptr, nullptr, M_ROWS, C_, C_);
    }
}

// round 14
// speedup vs baseline: 1.1556x; 1.1236x over previous
#include <cuda_runtime.h>
#include <cuda.h>
#include <cuda_fp16.h>
#include <cstdint>

// Problem dims (fixed per reference)
#define B_  2
#define T_  2048
#define C_  1024
#define H_  16
#define HD_ 64
#define C3_ 3072
#define M_ROWS (B_ * T_)   // 4096

// ---------------------------------------------------------------------------
// Scratch (allocation-free rule: device globals)   fp16 2-term scheme
// ---------------------------------------------------------------------------
__device__ __half g_qkvh[M_ROWS * C3_];
__device__ __half g_qkvl[M_ROWS * C3_];
__device__ __half g_xh[M_ROWS * C_];
__device__ __half g_xl[M_ROWS * C_];
__device__ __half g_wah[C3_ * C_];        // W_attn^T fp16 [3072, 1024]
__device__ __half g_wph[C_ * C_];         // W_proj^T fp16 [1024, 1024]
__device__ __half g_ah[M_ROWS * C_];
__device__ __half g_al[M_ROWS * C_];

// ---------------------------------------------------------------------------
__device__ __forceinline__ uint32_t smem_u32(const void* p) {
    uint32_t a;
    asm("{ .reg .u64 t; cvta.to.shared.u64 t, %1; cvt.u32.u64 %0, t; }" : "=r"(a) : "l"(p));
    return a;
}
__device__ __forceinline__ void cp_async16(uint32_t saddr, const void* gaddr) {
    asm volatile("cp.async.cg.shared.global [%0], [%1], 16;" :: "r"(saddr), "l"(gaddr));
}
__device__ __forceinline__ void cp_commit() {
    asm volatile("cp.async.commit_group;" ::: "memory");
}
template <int N>
__device__ __forceinline__ void cp_wait() {
    asm volatile("cp.async.wait_group %0;" :: "n"(N) : "memory");
}
__device__ __forceinline__ void ldm_x4(uint32_t& r0, uint32_t& r1, uint32_t& r2, uint32_t& r3,
                                       uint32_t addr) {
    asm volatile("ldmatrix.sync.aligned.m8n8.x4.shared.b16 {%0,%1,%2,%3}, [%4];"
                 : "=r"(r0), "=r"(r1), "=r"(r2), "=r"(r3) : "r"(addr));
}
__device__ __forceinline__ void ldm_x4_t(uint32_t& r0, uint32_t& r1, uint32_t& r2, uint32_t& r3,
                                         uint32_t addr) {
    asm volatile("ldmatrix.sync.aligned.m8n8.x4.trans.shared.b16 {%0,%1,%2,%3}, [%4];"
                 : "=r"(r0), "=r"(r1), "=r"(r2), "=r"(r3) : "r"(addr));
}
__device__ __forceinline__ void mma_f16(float* c, uint32_t a0, uint32_t a1, uint32_t a2,
                                        uint32_t a3, uint32_t b0, uint32_t b1) {
    asm volatile(
        "mma.sync.aligned.m16n8k16.row.col.f32.f16.f16.f32 "
        "{%0,%1,%2,%3}, {%4,%5,%6,%7}, {%8,%9}, {%0,%1,%2,%3};"
        : "+f"(c[0]), "+f"(c[1]), "+f"(c[2]), "+f"(c[3])
        : "r"(a0), "r"(a1), "r"(a2), "r"(a3), "r"(b0), "r"(b1));
}
__device__ __forceinline__ uint32_t pack_f16(float lo_elem, float hi_elem) {
    __half2 t = __floats2half2_rn(lo_elem, hi_elem);
    return *(uint32_t*)&t;
}
__device__ __forceinline__ float f16_residual(float v) {
    return v - __half2float(__float2half(v));
}

// mbarrier + TMA (sm_90 baseline features)
#define MBAR_INIT(a, n) asm volatile("mbarrier.init.shared.b64 [%0], %1;" :: "r"(a), "r"(n) : "memory")
#define MBAR_EXPECT_TX(a, n) \
    asm volatile("mbarrier.arrive.expect_tx.shared.b64 _, [%0], %1;" :: "r"(a), "r"(n) : "memory")
#define MBAR_WAIT(a, ph) do {                                                       \
    uint32_t _m = (a), _p = (ph), _d;                                               \
    asm volatile("{\n\t.reg .pred p;\n\t"                                           \
        "mbarrier.try_wait.parity.acquire.cta.shared::cta.b64 p, [%1], %2;\n\t"     \
        "selp.b32 %0, 1, 0, p;\n\t}" : "=r"(_d) : "r"(_m), "r"(_p) : "memory");     \
    if (!_d) {                                                                      \
        asm volatile("{\n\t.reg .pred P1;\n\t"                                      \
            "WL_%=:\n\t"                                                            \
            "mbarrier.try_wait.parity.acquire.cta.shared::cta.b64 P1, [%0], %1, 0x989680;\n\t" \
            "@P1 bra.uni WD_%=;\n\t"                                                \
            "bra.uni WL_%=;\n\t"                                                    \
            "WD_%=:\n\t}" :: "r"(_m), "r"(_p) : "memory");                          \
    } } while (0)
#define TMA_LOAD_2D(saddr, mapp, cx, cy, mbar) \
    asm volatile("cp.async.bulk.tensor.2d.shared::cta.global.tile.mbarrier::complete_tx::bytes " \
        "[%0], [%1, {%2, %3}], [%4];" \
        :: "r"(saddr), "l"(mapp), "r"(cx), "r"(cy), "r"(mbar) : "memory")
#define SWZ128(o) ((o) ^ (((o) >> 3) & 0x70))

// ---------------------------------------------------------------------------
// Split fp32 -> (hi, lo) fp16
// ---------------------------------------------------------------------------
__global__ __launch_bounds__(256) void split_kernel(
    const float* __restrict__ in, __half* __restrict__ hi,
    __half* __restrict__ lo, int n4)
{
    int i = blockIdx.x * blockDim.x + threadIdx.x;
    if (i >= n4) return;
    float4 v = ((const float4*)in)[i];
    float h0 = __half2float(__float2half(v.x));
    float h1 = __half2float(__float2half(v.y));
    float h2 = __half2float(__float2half(v.z));
    float h3 = __half2float(__float2half(v.w));
    uint32_t* ph = (uint32_t*)hi + i * 2;
    uint32_t* pl = (uint32_t*)lo + i * 2;
    ph[0] = pack_f16(v.x, v.y);  ph[1] = pack_f16(v.z, v.w);
    pl[0] = pack_f16(v.x - h0, v.y - h1);
    pl[1] = pack_f16(v.z - h2, v.w - h3);
}

// Transpose + fp16 round: in [K,N] fp32 -> hiT [N,K] fp16
__global__ __launch_bounds__(256) void transpose_f16_kernel(
    const float* __restrict__ in, __half* __restrict__ hiT, int K, int N)
{
    __shared__ float t[32][33];
    int n0 = blockIdx.x * 32, k0 = blockIdx.y * 32;
    int tx = threadIdx.x, ty = threadIdx.y;   // 32 x 8
#pragma unroll
    for (int i = 0; i < 32; i += 8)
        t[ty + i][tx] = in[(size_t)(k0 + ty + i) * N + n0 + tx];
    __syncthreads();
#pragma unroll
    for (int i = 0; i < 32; i += 8) {
        size_t o = (size_t)(n0 + ty + i) * K + k0 + tx;
        hiT[o] = __float2half(t[tx][ty + i]);
    }
}

// ---------------------------------------------------------------------------
// fp16 2-term GEMM, TMA-fed:  C[M,N] = (Ah+Al)[M,K] @ Bh[N,K]^T
// 128x128 tile, BK=64, SW128 smem layout (128B rows), 2-stage mbarrier pipe.
// 3 TMA loads per chunk (vs 1536 cp.async) -> LSU freed, tensor-bound.
// ---------------------------------------------------------------------------
#define TM_BK 64
#define TM_TILE_B 16384                 // 128 rows x 128 bytes
#define TM_STAGE_B (3 * TM_TILE_B)      // Ah, Al, Bh = 49152
#define TM_NSTG 2
#define SMEM_GEMM (TM_NSTG * TM_STAGE_B + 1024)   // +1024 for alignment

template <bool SPLIT>
__global__ __launch_bounds__(256, 2) void gemm_tma_kernel(
    const __grid_constant__ CUtensorMap tmAh,
    const __grid_constant__ CUtensorMap tmAl,
    const __grid_constant__ CUtensorMap tmBh,
    float* __restrict__ Cm, __half* __restrict__ Ch,
    __half* __restrict__ Cl, int M, int N, int K)
{
    extern __shared__ char smem_raw[];
    __shared__ uint64_t mbar_s[TM_NSTG];
    const uint32_t sb = (smem_u32(smem_raw) + 1023u) & ~1023u;
    const uint32_t mb0 = smem_u32(&mbar_s[0]);
    const int tid = threadIdx.x;
    const int wid = tid >> 5, lane = tid & 31;
    const int warp_m = wid >> 1;        // 0..3 -> 32 rows
    const int warp_n = wid & 1;         // 0..1 -> 64 cols
    const int m0 = blockIdx.y * 128;
    const int n0 = blockIdx.x * 128;

    if (tid == 0) {
        MBAR_INIT(mb0, 1);
        MBAR_INIT(mb0 + 8, 1);
    }
    __syncthreads();

    auto issue_stage = [&](int s, int ch) {
        uint32_t mb = mb0 + s * 8;
        uint32_t base = sb + s * TM_STAGE_B;
        MBAR_EXPECT_TX(mb, TM_STAGE_B);
        int cx = ch * TM_BK;
        TMA_LOAD_2D(base,                 (const void*)&tmAh, cx, m0, mb);
        TMA_LOAD_2D(base + TM_TILE_B,     (const void*)&tmAl, cx, m0, mb);
        TMA_LOAD_2D(base + 2 * TM_TILE_B, (const void*)&tmBh, cx, n0, mb);
    };

    float acc[2][8][4];
#pragma unroll
    for (int i = 0; i < 2; i++)
#pragma unroll
        for (int j = 0; j < 8; j++)
#pragma unroll
            for (int q = 0; q < 4; q++) acc[i][j][q] = 0.f;

    const int lrow = lane & 15;
    const int lcol = (lane >> 4) << 3;

    auto compute_stage = [&](int s) {
        uint32_t base = sb + s * TM_STAGE_B;
        uint32_t sAh = base, sAl = base + TM_TILE_B, sBh = base + 2 * TM_TILE_B;
#pragma unroll
        for (int ks = 0; ks < 4; ks++) {
            const int kb = (ks * 16 + lcol) * 2;    // byte col within 128B row
            uint32_t ahf[2][4], alf[2][4];
#pragma unroll
            for (int mi = 0; mi < 2; mi++) {
                int r = warp_m * 32 + mi * 16 + lrow;
                uint32_t off = SWZ128((uint32_t)(r * 128 + kb));
                ldm_x4(ahf[mi][0], ahf[mi][1], ahf[mi][2], ahf[mi][3], sAh + off);
                ldm_x4(alf[mi][0], alf[mi][1], alf[mi][2], alf[mi][3], sAl + off);
            }
            uint32_t bf[4][4];
#pragma unroll
            for (int nt = 0; nt < 4; nt++) {
                int r = warp_n * 64 + nt * 16 + lrow;
                uint32_t off = SWZ128((uint32_t)(r * 128 + kb));
                ldm_x4(bf[nt][0], bf[nt][1], bf[nt][2], bf[nt][3], sBh + off);
            }
            // hi pass: 16 MMAs, distinct accumulators
#pragma unroll
            for (int nt = 0; nt < 4; nt++)
#pragma unroll
                for (int mi = 0; mi < 2; mi++) {
                    mma_f16(acc[mi][nt * 2],     ahf[mi][0], ahf[mi][1], ahf[mi][2], ahf[mi][3],
                            bf[nt][0], bf[nt][2]);
                    mma_f16(acc[mi][nt * 2 + 1], ahf[mi][0], ahf[mi][1], ahf[mi][2], ahf[mi][3],
                            bf[nt][1], bf[nt][3]);
                }
            // lo pass
#pragma unroll
            for (int nt = 0; nt < 4; nt++)
#pragma unroll
                for (int mi = 0; mi < 2; mi++) {
                    mma_f16(acc[mi][nt * 2],     alf[mi][0], alf[mi][1], alf[mi][2], alf[mi][3],
                            bf[nt][0], bf[nt][2]);
                    mma_f16(acc[mi][nt * 2 + 1], alf[mi][0], alf[mi][1], alf[mi][2], alf[mi][3],
                            bf[nt][1], bf[nt][3]);
                }
        }
    };

    const int nch = K / TM_BK;     // 16 for K=1024
    if (tid == 0) {
        issue_stage(0, 0);
        issue_stage(1, 1);
    }
    int phase[TM_NSTG] = {0, 0};
    for (int ch = 0; ch < nch; ch++) {
        const int s = ch & 1;
        MBAR_WAIT(mb0 + s * 8, phase[s]);
        phase[s] ^= 1;
        compute_stage(s);
        __syncthreads();               // all warps done reading stage s
        if (ch + 2 < nch && tid == 0) issue_stage(s, ch + 2);
    }

    const int gid = lane >> 2;
    const int tig = lane & 3;
#pragma unroll
    for (int mi = 0; mi < 2; mi++) {
        int rbase = m0 + warp_m * 32 + mi * 16 + gid;
#pragma unroll
        for (int ni = 0; ni < 8; ni++) {
            int col = n0 + warp_n * 64 + ni * 8 + tig * 2;
            if (SPLIT) {
                float v0 = acc[mi][ni][0], v1 = acc[mi][ni][1];
                float v2 = acc[mi][ni][2], v3 = acc[mi][ni][3];
                *(uint32_t*)(Ch + (size_t)rbase * N + col) = pack_f16(v0, v1);
                *(uint32_t*)(Cl + (size_t)rbase * N + col) =
                    pack_f16(f16_residual(v0), f16_residual(v1));
                *(uint32_t*)(Ch + (size_t)(rbase + 8) * N + col) = pack_f16(v2, v3);
                *(uint32_t*)(Cl + (size_t)(rbase + 8) * N + col) =
                    pack_f16(f16_residual(v2), f16_residual(v3));
            } else {
                float* p0 = Cm + (size_t)rbase * N + col;
                float* p1 = Cm + (size_t)(rbase + 8) * N + col;
                p0[0] = acc[mi][ni][0]; p0[1] = acc[mi][ni][1];
                p1[0] = acc[mi][ni][2]; p1[1] = acc[mi][ni][3];
            }
        }
    }
}

// ---------------------------------------------------------------------------
// fp16 2-term flash attention (unchanged from round 13 known-good)
// ---------------------------------------------------------------------------
#define AT_LD 72
#define AT_QT_B (128 * AT_LD * 2)
#define AT_KV_T (64 * AT_LD * 2)
#define AT_STG  (2 * AT_KV_T)
#define AT_NSTG 3
#define SMEM_ATTN (2 * AT_QT_B + AT_NSTG * AT_STG)   // 92160

__global__ __launch_bounds__(256, 1) void attn_mma_kernel(
    const __half* __restrict__ qkvh, const __half* __restrict__ qkvl,
    __half* __restrict__ ah, __half* __restrict__ al)
{
    extern __shared__ char smem[];
    const uint32_t sb = smem_u32(smem);
    const int tid = threadIdx.x;
    const int wid = tid >> 5, lane = tid & 31;
    const int qt = (int)gridDim.x - 1 - (int)blockIdx.x;
    const int bh = blockIdx.y;
    const int b = bh >> 4, h = bh & 15;
    const int q0 = qt * 128;

    const uint32_t sQh = sb, sQl = sb + AT_QT_B;
    const uint32_t stg0 = sb + 2 * AT_QT_B;

    const int niters = 2 * qt + 2;

#pragma unroll
    for (int i = 0; i < 8; i++) {
        int chunk = tid + i * 256;
        int isLo = chunk >> 10;
        int c2 = chunk & 1023;
        int row = c2 >> 3, seg = c2 & 7;
        const __half* src = (isLo ? qkvl : qkvh) +
            (size_t)(b * T_ + q0 + row) * C3_ + h * HD_ + seg * 8;
        cp_async16((isLo ? sQl : sQh) + (uint32_t)(row * AT_LD + seg * 8) * 2, src);
    }
    cp_commit();

    auto load_kv = [&](int s, int it) {
        const int k0 = it * 64;
        uint32_t sbase = stg0 + s * AT_STG;
#pragma unroll
        for (int i = 0; i < 4; i++) {
            int chunk = tid + i * 256;
            int t2 = chunk >> 9;
            int c2 = chunk & 511;
            int row = c2 >> 3, seg = c2 & 7;
            size_t coloff = (t2 == 0) ? (size_t)(C_ + h * HD_) : (size_t)(2 * C_ + h * HD_);
            cp_async16(sbase + t2 * AT_KV_T + (uint32_t)(row * AT_LD + seg * 8) * 2,
                       qkvh + (size_t)(b * T_ + k0 + row) * C3_ + coloff + seg * 8);
        }
    };
    load_kv(0, 0);
    cp_commit();
    load_kv(1, 1);
    cp_commit();

    const int lrow = lane & 15;
    const int lcol = (lane >> 4) << 3;
    const int gid = lane >> 2;
    const int tig = lane & 3;

    cp_wait<1>();
    __syncthreads();

    uint32_t qh[4][4], ql[4][4];
#pragma unroll
    for (int kt = 0; kt < 4; kt++) {
        uint32_t off = (uint32_t)((wid * 16 + lrow) * AT_LD + kt * 16 + lcol) * 2;
        ldm_x4(qh[kt][0], qh[kt][1], qh[kt][2], qh[kt][3], sQh + off);
        ldm_x4(ql[kt][0], ql[kt][1], ql[kt][2], ql[kt][3], sQl + off);
    }

    float o[8][4];
#pragma unroll
    for (int i = 0; i < 8; i++)
#pragma unroll
        for (int j = 0; j < 4; j++) o[i][j] = 0.f;
    float m0r = -1e30f, m1r = -1e30f, l0r = 0.f, l1r = 0.f;

    for (int it = 0; it < niters; it++) {
        if (it > 0) {
            cp_wait<1>();
            __syncthreads();
        }

        const uint32_t s_ = stg0 + (it % AT_NSTG) * AT_STG;
        const uint32_t sKh = s_, sVh = s_ + AT_KV_T;
        const int k0 = it * 64;
        const bool active = (q0 + wid * 16 + 15 >= k0);

        if (active) {
            float s[8][4];
#pragma unroll
            for (int i = 0; i < 8; i++)
#pragma unroll
                for (int j = 0; j < 4; j++) s[i][j] = 0.f;

#pragma unroll
            for (int kt = 0; kt < 4; kt++) {
                uint32_t kf[4][4];
#pragma unroll
                for (int np = 0; np < 4; np++) {
                    uint32_t boff = (uint32_t)((np * 16 + lrow) * AT_LD + kt * 16 + lcol) * 2;
                    ldm_x4(kf[np][0], kf[np][1], kf[np][2], kf[np][3], sKh + boff);
                }
#pragma unroll
                for (int np = 0; np < 4; np++) {
                    mma_f16(s[np * 2],     qh[kt][0], qh[kt][1], qh[kt][2], qh[kt][3],
                            kf[np][0], kf[np][2]);
                    mma_f16(s[np * 2 + 1], qh[kt][0], qh[kt][1], qh[kt][2], qh[kt][3],
                            kf[np][1], kf[np][3]);
                }
#pragma unroll
                for (int np = 0; np < 4; np++) {
                    mma_f16(s[np * 2],     ql[kt][0], ql[kt][1], ql[kt][2], ql[kt][3],
                            kf[np][0], kf[np][2]);
                    mma_f16(s[np * 2 + 1], ql[kt][0], ql[kt][1], ql[kt][2], ql[kt][3],
                            kf[np][1], kf[np][3]);
                }
            }

#pragma unroll
            for (int ni = 0; ni < 8; ni++)
#pragma unroll
                for (int e = 0; e < 4; e++) s[ni][e] *= 0.125f;
            if (it == 0 && tig == 0) { s[0][0] += 1.0f; s[0][2] += 1.0f; }
            const int grow0 = q0 + wid * 16 + gid;
            const int grow1 = grow0 + 8;
            if (k0 + 63 > q0 + wid * 16) {
#pragma unroll
                for (int ni = 0; ni < 8; ni++) {
                    int gc = k0 + ni * 8 + tig * 2;
                    if (gc > grow0)     s[ni][0] = -1e30f;
                    if (gc + 1 > grow0) s[ni][1] = -1e30f;
                    if (gc > grow1)     s[ni][2] = -1e30f;
                    if (gc + 1 > grow1) s[ni][3] = -1e30f;
                }
            }

            float mx0 = s[0][0], mx1 = s[0][2];
#pragma unroll
            for (int ni = 0; ni < 8; ni++) {
                mx0 = fmaxf(mx0, fmaxf(s[ni][0], s[ni][1]));
                mx1 = fmaxf(mx1, fmaxf(s[ni][2], s[ni][3]));
            }
            mx0 = fmaxf(mx0, __shfl_xor_sync(0xffffffffu, mx0, 1));
            mx0 = fmaxf(mx0, __shfl_xor_sync(0xffffffffu, mx0, 2));
            mx1 = fmaxf(mx1, __shfl_xor_sync(0xffffffffu, mx1, 1));
            mx1 = fmaxf(mx1, __shfl_xor_sync(0xffffffffu, mx1, 2));
            float mn0 = fmaxf(m0r, mx0), mn1 = fmaxf(m1r, mx1);
            float a0 = __expf(m0r - mn0), a1 = __expf(m1r - mn1);
            m0r = mn0; m1r = mn1;
            float sum0 = 0.f, sum1 = 0.f;
#pragma unroll
            for (int ni = 0; ni < 8; ni++) {
                s[ni][0] = __expf(s[ni][0] - mn0);
                s[ni][1] = __expf(s[ni][1] - mn0);
                s[ni][2] = __expf(s[ni][2] - mn1);
                s[ni][3] = __expf(s[ni][3] - mn1);
                sum0 += s[ni][0] + s[ni][1];
                sum1 += s[ni][2] + s[ni][3];
            }
            sum0 += __shfl_xor_sync(0xffffffffu, sum0, 1);
            sum0 += __shfl_xor_sync(0xffffffffu, sum0, 2);
            sum1 += __shfl_xor_sync(0xffffffffu, sum1, 1);
            sum1 += __shfl_xor_sync(0xffffffffu, sum1, 2);
            l0r = l0r * a0 + sum0;
            l1r = l1r * a1 + sum1;

#pragma unroll
            for (int ni = 0; ni < 8; ni++) {
                o[ni][0] *= a0; o[ni][1] *= a0;
                o[ni][2] *= a1; o[ni][3] *= a1;
            }

#pragma unroll
            for (int kt = 0; kt < 4; kt++) {
                uint32_t ph[4], pl[4];
                {
                    float v0 = s[2 * kt][0], v1 = s[2 * kt][1];
                    float v2 = s[2 * kt][2], v3 = s[2 * kt][3];
                    float w0 = s[2 * kt + 1][0], w1 = s[2 * kt + 1][1];
                    float w2 = s[2 * kt + 1][2], w3 = s[2 * kt + 1][3];
                    ph[0] = pack_f16(v0, v1); ph[1] = pack_f16(v2, v3);
                    ph[2] = pack_f16(w0, w1); ph[3] = pack_f16(w2, w3);
                    pl[0] = pack_f16(f16_residual(v0), f16_residual(v1));
                    pl[1] = pack_f16(f16_residual(v2), f16_residual(v3));
                    pl[2] = pack_f16(f16_residual(w0), f16_residual(w1));
                    pl[3] = pack_f16(f16_residual(w2), f16_residual(w3));
                }
                uint32_t vf[4][4];
#pragma unroll
                for (int dp = 0; dp < 4; dp++) {
                    uint32_t voff = (uint32_t)((kt * 16 + lrow) * AT_LD + dp * 16 + lcol) * 2;
                    ldm_x4_t(vf[dp][0], vf[dp][1], vf[dp][2], vf[dp][3], sVh + voff);
                }
#pragma unroll
                for (int dp = 0; dp < 4; dp++) {
                    mma_f16(o[dp * 2],     ph[0], ph[1], ph[2], ph[3], vf[dp][0], vf[dp][1]);
                    mma_f16(o[dp * 2 + 1], ph[0], ph[1], ph[2], ph[3], vf[dp][2], vf[dp][3]);
                }
#pragma unroll
                for (int dp = 0; dp < 4; dp++) {
                    mma_f16(o[dp * 2],     pl[0], pl[1], pl[2], pl[3], vf[dp][0], vf[dp][1]);
                    mma_f16(o[dp * 2 + 1], pl[0], pl[1], pl[2], pl[3], vf[dp][2], vf[dp][3]);
                }
            }
        }

        if (it + 2 < niters) load_kv((it + 2) % AT_NSTG, it + 2);
        cp_commit();
    }

    const float inv0 = 1.f / l0r, inv1 = 1.f / l1r;
    const int grow0 = q0 + wid * 16 + gid;
    const size_t r0o = (size_t)(b * T_ + grow0) * C_;
    const size_t r1o = (size_t)(b * T_ + grow0 + 8) * C_;
#pragma unroll
    for (int ni = 0; ni < 8; ni++) {
        int col = h * HD_ + ni * 8 + tig * 2;
        float v0 = o[ni][0] * inv0, v1 = o[ni][1] * inv0;
        float v2 = o[ni][2] * inv1, v3 = o[ni][3] * inv1;
        *(uint32_t*)(ah + r0o + col) = pack_f16(v0, v1);
        *(uint32_t*)(al + r0o + col) = pack_f16(f16_residual(v0), f16_residual(v1));
        *(uint32_t*)(ah + r1o + col) = pack_f16(v2, v3);
        *(uint32_t*)(al + r1o + col) = pack_f16(f16_residual(v2), f16_residual(v3));
    }
}

// ---------------------------------------------------------------------------
// Host: tensormap construction via driver entry point (no -lcuda needed)
// ---------------------------------------------------------------------------
typedef CUresult (*EncodeTiledFn)(
    CUtensorMap*, CUtensorMapDataType, cuuint32_t, void*,
    const cuuint64_t*, const cuuint64_t*, const cuuint32_t*, const cuuint32_t*,
    CUtensorMapInterleave, CUtensorMapSwizzle, CUtensorMapL2promotion,
    CUtensorMapFloatOOBfill);

static void make_map2d(EncodeTiledFn fn, CUtensorMap* m, void* base, int rows, int K) {
    cuuint64_t dims[2]    = {(cuuint64_t)K, (cuuint64_t)rows};
    cuuint64_t strides[1] = {(cuuint64_t)K * 2};
    cuuint32_t box[2]     = {64, 128};          // 64 halfs = 128B per row (SW128)
    cuuint32_t estr[2]    = {1, 1};
    fn(m, CU_TENSOR_MAP_DATA_TYPE_FLOAT16, 2, base, dims, strides, box, estr,
       CU_TENSOR_MAP_INTERLEAVE_NONE, CU_TENSOR_MAP_SWIZZLE_128B,
       CU_TENSOR_MAP_L2_PROMOTION_L2_128B, CU_TENSOR_MAP_FLOAT_OOB_FILL_NONE);
}

extern "C" void kernel_launch(void* const* d_in, const int* in_sizes, int n_in,
                              void* d_out, int out_size)
{
    const float* x  = (const float*)d_in[0];
    const float* Wa = (const float*)d_in[1];
    const float* Wp = (const float*)d_in[2];
    float* y = (float*)d_out;

    __half *qkvh, *qkvl, *xh, *xl, *wah, *wph, *ah, *al;
    cudaGetSymbolAddress((void**)&qkvh, g_qkvh);
    cudaGetSymbolAddress((void**)&qkvl, g_qkvl);
    cudaGetSymbolAddress((void**)&xh, g_xh);
    cudaGetSymbolAddress((void**)&xl, g_xl);
    cudaGetSymbolAddress((void**)&wah, g_wah);
    cudaGetSymbolAddress((void**)&wph, g_wph);
    cudaGetSymbolAddress((void**)&ah, g_ah);
    cudaGetSymbolAddress((void**)&al, g_al);

    EncodeTiledFn enc = nullptr;
    cudaDriverEntryPointQueryResult qr;
#if CUDART_VERSION >= 12050
    cudaGetDriverEntryPointByVersion("cuTensorMapEncodeTiled", (void**)&enc, 12000,
                                     cudaEnableDefault, &qr);
#else
    cudaGetDriverEntryPoint("cuTensorMapEncodeTiled", (void**)&enc,
                            cudaEnableDefault, &qr);
#endif

    CUtensorMap m_xh, m_xl, m_wa, m_ah, m_al, m_wp;
    make_map2d(enc, &m_xh, xh,  M_ROWS, C_);
    make_map2d(enc, &m_xl, xl,  M_ROWS, C_);
    make_map2d(enc, &m_wa, wah, C3_,    C_);
    make_map2d(enc, &m_ah, ah,  M_ROWS, C_);
    make_map2d(enc, &m_al, al,  M_ROWS, C_);
    make_map2d(enc, &m_wp, wph, C_,     C_);

    cudaFuncSetAttribute(gemm_tma_kernel<true>,
                         cudaFuncAttributeMaxDynamicSharedMemorySize, SMEM_GEMM);
    cudaFuncSetAttribute(gemm_tma_kernel<false>,
                         cudaFuncAttributeMaxDynamicSharedMemorySize, SMEM_GEMM);
    cudaFuncSetAttribute(attn_mma_kernel,
                         cudaFuncAttributeMaxDynamicSharedMemorySize, SMEM_ATTN);

    // 1) splits / weight transposes
    {
        int n4 = M_ROWS * C_ / 4;
        split_kernel<<<(n4 + 255) / 256, 256>>>(x, xh, xl, n4);
        dim3 grid_a(C3_ / 32, C_ / 32);
        transpose_f16_kernel<<<grid_a, dim3(32, 8)>>>(Wa, wah, C_, C3_);
        dim3 grid_p(C_ / 32, C_ / 32);
        transpose_f16_kernel<<<grid_p, dim3(32, 8)>>>(Wp, wph, C_, C_);
    }

    // 2) qkv = x @ W_attn -> fp16 hi/lo
    {
        dim3 grid(C3_ / 128, M_ROWS / 128);
        gemm_tma_kernel<true><<<grid, 256, SMEM_GEMM>>>(
            m_xh, m_xl, m_wa, nullptr, qkvh, qkvl, M_ROWS, C3_, C_);
    }

    // 3) flash attention -> fp16 hi/lo
    {
        dim3 grid(T_ / 128, B_ * H_);
        attn_mma_kernel<<<grid, 256, SMEM_ATTN>>>(qkvh, qkvl, ah, al);
    }

    // 4) y = att @ W_proj (fp32 out)
    {
        dim3 grid(C_ / 128, M_ROWS / 128);
        gemm_tma_kernel<false><<<grid, 256, SMEM_GEMM>>>(
            m_ah, m_al, m_wp, y, nullptr, nullptr, M_ROWS, C_, C_);
    }
}

// round 15
// speedup vs baseline: 1.1742x; 1.0161x over previous
#include <cuda_runtime.h>
#include <cuda.h>
#include <cuda_fp16.h>
#include <cstdint>

// Problem dims (fixed per reference)
#define B_  2
#define T_  2048
#define C_  1024
#define H_  16
#define HD_ 64
#define C3_ 3072
#define M_ROWS (B_ * T_)   // 4096

// ---------------------------------------------------------------------------
// Scratch (allocation-free rule: device globals)   fp16 2-term scheme
// ---------------------------------------------------------------------------
__device__ __half g_qkvh[M_ROWS * C3_];
__device__ __half g_qkvl[M_ROWS * C3_];
__device__ __half g_xh[M_ROWS * C_];
__device__ __half g_xl[M_ROWS * C_];
__device__ __half g_wah[C3_ * C_];        // W_attn^T fp16 [3072, 1024]
__device__ __half g_wph[C_ * C_];         // W_proj^T fp16 [1024, 1024]
__device__ __half g_ah[M_ROWS * C_];
__device__ __half g_al[M_ROWS * C_];

// ---------------------------------------------------------------------------
__device__ __forceinline__ uint32_t smem_u32(const void* p) {
    uint32_t a;
    asm("{ .reg .u64 t; cvta.to.shared.u64 t, %1; cvt.u32.u64 %0, t; }" : "=r"(a) : "l"(p));
    return a;
}
__device__ __forceinline__ void ldm_x4(uint32_t& r0, uint32_t& r1, uint32_t& r2, uint32_t& r3,
                                       uint32_t addr) {
    asm volatile("ldmatrix.sync.aligned.m8n8.x4.shared.b16 {%0,%1,%2,%3}, [%4];"
                 : "=r"(r0), "=r"(r1), "=r"(r2), "=r"(r3) : "r"(addr));
}
__device__ __forceinline__ void ldm_x4_t(uint32_t& r0, uint32_t& r1, uint32_t& r2, uint32_t& r3,
                                         uint32_t addr) {
    asm volatile("ldmatrix.sync.aligned.m8n8.x4.trans.shared.b16 {%0,%1,%2,%3}, [%4];"
                 : "=r"(r0), "=r"(r1), "=r"(r2), "=r"(r3) : "r"(addr));
}
__device__ __forceinline__ void mma_f16(float* c, uint32_t a0, uint32_t a1, uint32_t a2,
                                        uint32_t a3, uint32_t b0, uint32_t b1) {
    asm volatile(
        "mma.sync.aligned.m16n8k16.row.col.f32.f16.f16.f32 "
        "{%0,%1,%2,%3}, {%4,%5,%6,%7}, {%8,%9}, {%0,%1,%2,%3};"
        : "+f"(c[0]), "+f"(c[1]), "+f"(c[2]), "+f"(c[3])
        : "r"(a0), "r"(a1), "r"(a2), "r"(a3), "r"(b0), "r"(b1));
}
__device__ __forceinline__ uint32_t pack_f16(float lo_elem, float hi_elem) {
    __half2 t = __floats2half2_rn(lo_elem, hi_elem);
    return *(uint32_t*)&t;
}
__device__ __forceinline__ float f16_residual(float v) {
    return v - __half2float(__float2half(v));
}

// mbarrier + TMA (sm_90 baseline features)
#define MBAR_INIT(a, n) asm volatile("mbarrier.init.shared.b64 [%0], %1;" :: "r"(a), "r"(n) : "memory")
#define MBAR_EXPECT_TX(a, n) \
    asm volatile("mbarrier.arrive.expect_tx.shared.b64 _, [%0], %1;" :: "r"(a), "r"(n) : "memory")
#define MBAR_WAIT(a, ph) do {                                                       \
    uint32_t _m = (a), _p = (ph), _d;                                               \
    asm volatile("{\n\t.reg .pred p;\n\t"                                           \
        "mbarrier.try_wait.parity.acquire.cta.shared::cta.b64 p, [%1], %2;\n\t"     \
        "selp.b32 %0, 1, 0, p;\n\t}" : "=r"(_d) : "r"(_m), "r"(_p) : "memory");     \
    if (!_d) {                                                                      \
        asm volatile("{\n\t.reg .pred P1;\n\t"                                      \
            "WL_%=:\n\t"                                                            \
            "mbarrier.try_wait.parity.acquire.cta.shared::cta.b64 P1, [%0], %1, 0x989680;\n\t" \
            "@P1 bra.uni WD_%=;\n\t"                                                \
            "bra.uni WL_%=;\n\t"                                                    \
            "WD_%=:\n\t}" :: "r"(_m), "r"(_p) : "memory");                          \
    } } while (0)
#define TMA_LOAD_2D(saddr, mapp, cx, cy, mbar) \
    asm volatile("cp.async.bulk.tensor.2d.shared::cta.global.tile.mbarrier::complete_tx::bytes " \
        "[%0], [%1, {%2, %3}], [%4];" \
        :: "r"(saddr), "l"(mapp), "r"(cx), "r"(cy), "r"(mbar) : "memory")
#define SWZ128(o) ((o) ^ (((o) >> 3) & 0x70))

// ---------------------------------------------------------------------------
// Split fp32 -> (hi, lo) fp16
// ---------------------------------------------------------------------------
__global__ __launch_bounds__(256) void split_kernel(
    const float* __restrict__ in, __half* __restrict__ hi,
    __half* __restrict__ lo, int n4)
{
    int i = blockIdx.x * blockDim.x + threadIdx.x;
    if (i >= n4) return;
    float4 v = ((const float4*)in)[i];
    float h0 = __half2float(__float2half(v.x));
    float h1 = __half2float(__float2half(v.y));
    float h2 = __half2float(__float2half(v.z));
    float h3 = __half2float(__float2half(v.w));
    uint32_t* ph = (uint32_t*)hi + i * 2;
    uint32_t* pl = (uint32_t*)lo + i * 2;
    ph[0] = pack_f16(v.x, v.y);  ph[1] = pack_f16(v.z, v.w);
    pl[0] = pack_f16(v.x - h0, v.y - h1);
    pl[1] = pack_f16(v.z - h2, v.w - h3);
}

// Transpose + fp16 round: in [K,N] fp32 -> hiT [N,K] fp16
__global__ __launch_bounds__(256) void transpose_f16_kernel(
    const float* __restrict__ in, __half* __restrict__ hiT, int K, int N)
{
    __shared__ float t[32][33];
    int n0 = blockIdx.x * 32, k0 = blockIdx.y * 32;
    int tx = threadIdx.x, ty = threadIdx.y;   // 32 x 8
#pragma unroll
    for (int i = 0; i < 32; i += 8)
        t[ty + i][tx] = in[(size_t)(k0 + ty + i) * N + n0 + tx];
    __syncthreads();
#pragma unroll
    for (int i = 0; i < 32; i += 8) {
        size_t o = (size_t)(n0 + ty + i) * K + k0 + tx;
        hiT[o] = __float2half(t[tx][ty + i]);
    }
}

// ---------------------------------------------------------------------------
// fp16 2-term GEMM, TMA-fed (unchanged from round 14 known-good)
// ---------------------------------------------------------------------------
#define TM_BK 64
#define TM_TILE_B 16384
#define TM_STAGE_B (3 * TM_TILE_B)
#define TM_NSTG 2
#define SMEM_GEMM (TM_NSTG * TM_STAGE_B + 1024)

template <bool SPLIT>
__global__ __launch_bounds__(256, 2) void gemm_tma_kernel(
    const __grid_constant__ CUtensorMap tmAh,
    const __grid_constant__ CUtensorMap tmAl,
    const __grid_constant__ CUtensorMap tmBh,
    float* __restrict__ Cm, __half* __restrict__ Ch,
    __half* __restrict__ Cl, int M, int N, int K)
{
    extern __shared__ char smem_raw[];
    __shared__ uint64_t mbar_s[TM_NSTG];
    const uint32_t sb = (smem_u32(smem_raw) + 1023u) & ~1023u;
    const uint32_t mb0 = smem_u32(&mbar_s[0]);
    const int tid = threadIdx.x;
    const int wid = tid >> 5, lane = tid & 31;
    const int warp_m = wid >> 1;
    const int warp_n = wid & 1;
    const int m0 = blockIdx.y * 128;
    const int n0 = blockIdx.x * 128;

    if (tid == 0) {
        MBAR_INIT(mb0, 1);
        MBAR_INIT(mb0 + 8, 1);
    }
    __syncthreads();

    auto issue_stage = [&](int s, int ch) {
        uint32_t mb = mb0 + s * 8;
        uint32_t base = sb + s * TM_STAGE_B;
        MBAR_EXPECT_TX(mb, TM_STAGE_B);
        int cx = ch * TM_BK;
        TMA_LOAD_2D(base,                 (const void*)&tmAh, cx, m0, mb);
        TMA_LOAD_2D(base + TM_TILE_B,     (const void*)&tmAl, cx, m0, mb);
        TMA_LOAD_2D(base + 2 * TM_TILE_B, (const void*)&tmBh, cx, n0, mb);
    };

    float acc[2][8][4];
#pragma unroll
    for (int i = 0; i < 2; i++)
#pragma unroll
        for (int j = 0; j < 8; j++)
#pragma unroll
            for (int q = 0; q < 4; q++) acc[i][j][q] = 0.f;

    const int lrow = lane & 15;
    const int lcol = (lane >> 4) << 3;

    auto compute_stage = [&](int s) {
        uint32_t base = sb + s * TM_STAGE_B;
        uint32_t sAh = base, sAl = base + TM_TILE_B, sBh = base + 2 * TM_TILE_B;
#pragma unroll
        for (int ks = 0; ks < 4; ks++) {
            const int kb = (ks * 16 + lcol) * 2;
            uint32_t ahf[2][4], alf[2][4];
#pragma unroll
            for (int mi = 0; mi < 2; mi++) {
                int r = warp_m * 32 + mi * 16 + lrow;
                uint32_t off = SWZ128((uint32_t)(r * 128 + kb));
                ldm_x4(ahf[mi][0], ahf[mi][1], ahf[mi][2], ahf[mi][3], sAh + off);
                ldm_x4(alf[mi][0], alf[mi][1], alf[mi][2], alf[mi][3], sAl + off);
            }
            uint32_t bf[4][4];
#pragma unroll
            for (int nt = 0; nt < 4; nt++) {
                int r = warp_n * 64 + nt * 16 + lrow;
                uint32_t off = SWZ128((uint32_t)(r * 128 + kb));
                ldm_x4(bf[nt][0], bf[nt][1], bf[nt][2], bf[nt][3], sBh + off);
            }
#pragma unroll
            for (int nt = 0; nt < 4; nt++)
#pragma unroll
                for (int mi = 0; mi < 2; mi++) {
                    mma_f16(acc[mi][nt * 2],     ahf[mi][0], ahf[mi][1], ahf[mi][2], ahf[mi][3],
                            bf[nt][0], bf[nt][2]);
                    mma_f16(acc[mi][nt * 2 + 1], ahf[mi][0], ahf[mi][1], ahf[mi][2], ahf[mi][3],
                            bf[nt][1], bf[nt][3]);
                }
#pragma unroll
            for (int nt = 0; nt < 4; nt++)
#pragma unroll
                for (int mi = 0; mi < 2; mi++) {
                    mma_f16(acc[mi][nt * 2],     alf[mi][0], alf[mi][1], alf[mi][2], alf[mi][3],
                            bf[nt][0], bf[nt][2]);
                    mma_f16(acc[mi][nt * 2 + 1], alf[mi][0], alf[mi][1], alf[mi][2], alf[mi][3],
                            bf[nt][1], bf[nt][3]);
                }
        }
    };

    const int nch = K / TM_BK;
    if (tid == 0) {
        issue_stage(0, 0);
        issue_stage(1, 1);
    }
    int phase[TM_NSTG] = {0, 0};
    for (int ch = 0; ch < nch; ch++) {
        const int s = ch & 1;
        MBAR_WAIT(mb0 + s * 8, phase[s]);
        phase[s] ^= 1;
        compute_stage(s);
        __syncthreads();
        if (ch + 2 < nch && tid == 0) issue_stage(s, ch + 2);
    }

    const int gid = lane >> 2;
    const int tig = lane & 3;
#pragma unroll
    for (int mi = 0; mi < 2; mi++) {
        int rbase = m0 + warp_m * 32 + mi * 16 + gid;
#pragma unroll
        for (int ni = 0; ni < 8; ni++) {
            int col = n0 + warp_n * 64 + ni * 8 + tig * 2;
            if (SPLIT) {
                float v0 = acc[mi][ni][0], v1 = acc[mi][ni][1];
                float v2 = acc[mi][ni][2], v3 = acc[mi][ni][3];
                *(uint32_t*)(Ch + (size_t)rbase * N + col) = pack_f16(v0, v1);
                *(uint32_t*)(Cl + (size_t)rbase * N + col) =
                    pack_f16(f16_residual(v0), f16_residual(v1));
                *(uint32_t*)(Ch + (size_t)(rbase + 8) * N + col) = pack_f16(v2, v3);
                *(uint32_t*)(Cl + (size_t)(rbase + 8) * N + col) =
                    pack_f16(f16_residual(v2), f16_residual(v3));
            } else {
                float* p0 = Cm + (size_t)rbase * N + col;
                float* p1 = Cm + (size_t)(rbase + 8) * N + col;
                p0[0] = acc[mi][ni][0]; p0[1] = acc[mi][ni][1];
                p1[0] = acc[mi][ni][2]; p1[1] = acc[mi][ni][3];
            }
        }
    }
}

// ---------------------------------------------------------------------------
// fp16 2-term flash attention, TMA-fed Q and KV. SW128 smem (128B rows).
// Q box {64,128} hi+lo; KV box {64,64} x 3 stages. Grid (T/128, B*H).
// ---------------------------------------------------------------------------
#define AQ_TILE 16384                  // 128 rows x 128 B
#define AKV_TILE 8192                  // 64 rows x 128 B
#define AKV_STG (2 * AKV_TILE)         // Kh, Vh = 16384
#define AT_NSTG 3
#define SMEM_ATTN (2 * AQ_TILE + AT_NSTG * AKV_STG + 1024)   // 82944

__global__ __launch_bounds__(256, 1) void attn_mma_kernel(
    const __grid_constant__ CUtensorMap tmQh,   // box {64,128} over qkvh
    const __grid_constant__ CUtensorMap tmQl,   // box {64,128} over qkvl
    const __grid_constant__ CUtensorMap tmKV,   // box {64,64}  over qkvh
    __half* __restrict__ ah, __half* __restrict__ al)
{
    extern __shared__ char smem_raw[];
    __shared__ uint64_t mbar_s[1 + AT_NSTG];
    const uint32_t sb = (smem_u32(smem_raw) + 1023u) & ~1023u;
    const uint32_t mbQ = smem_u32(&mbar_s[0]);
    const uint32_t mbKV = mbQ + 8;
    const int tid = threadIdx.x;
    const int wid = tid >> 5, lane = tid & 31;
    const int qt = (int)gridDim.x - 1 - (int)blockIdx.x;   // heavy blocks first
    const int bh = blockIdx.y;
    const int b = bh >> 4, h = bh & 15;
    const int q0 = qt * 128;

    const uint32_t sQh = sb, sQl = sb + AQ_TILE;
    const uint32_t stg0 = sb + 2 * AQ_TILE;
    const int niters = 2 * qt + 2;

    if (tid == 0) {
        MBAR_INIT(mbQ, 1);
#pragma unroll
        for (int s = 0; s < AT_NSTG; s++) MBAR_INIT(mbKV + s * 8, 1);
    }
    __syncthreads();

    auto issue_kv = [&](int s, int it) {
        uint32_t mb = mbKV + s * 8;
        uint32_t base = stg0 + s * AKV_STG;
        MBAR_EXPECT_TX(mb, AKV_STG);
        int cy = b * T_ + it * 64;
        TMA_LOAD_2D(base,            (const void*)&tmKV, C_ + h * HD_,     cy, mb);
        TMA_LOAD_2D(base + AKV_TILE, (const void*)&tmKV, 2 * C_ + h * HD_, cy, mb);
    };

    if (tid == 0) {
        MBAR_EXPECT_TX(mbQ, 2 * AQ_TILE);
        TMA_LOAD_2D(sQh, (const void*)&tmQh, h * HD_, b * T_ + q0, mbQ);
        TMA_LOAD_2D(sQl, (const void*)&tmQl, h * HD_, b * T_ + q0, mbQ);
        issue_kv(0, 0);
        issue_kv(1, 1);
    }

    const int lrow = lane & 15;
    const int lcol = (lane >> 4) << 3;
    const int gid = lane >> 2;
    const int tig = lane & 3;

    MBAR_WAIT(mbQ, 0);

    // --- Q fragments (persistent), swizzled rows ---
    uint32_t qh[4][4], ql[4][4];
#pragma unroll
    for (int kt = 0; kt < 4; kt++) {
        uint32_t off = SWZ128((uint32_t)((wid * 16 + lrow) * 128 + (kt * 16 + lcol) * 2));
        ldm_x4(qh[kt][0], qh[kt][1], qh[kt][2], qh[kt][3], sQh + off);
        ldm_x4(ql[kt][0], ql[kt][1], ql[kt][2], ql[kt][3], sQl + off);
    }

    float o[8][4];
#pragma unroll
    for (int i = 0; i < 8; i++)
#pragma unroll
        for (int j = 0; j < 4; j++) o[i][j] = 0.f;
    float m0r = -1e30f, m1r = -1e30f, l0r = 0.f, l1r = 0.f;

    for (int it = 0; it < niters; it++) {
        const int s = it % AT_NSTG;
        MBAR_WAIT(mbKV + s * 8, (it / AT_NSTG) & 1);

        const uint32_t sKh = stg0 + s * AKV_STG;
        const uint32_t sVh = sKh + AKV_TILE;
        const int k0 = it * 64;
        const bool active = (q0 + wid * 16 + 15 >= k0);

        if (active) {
            // ---- S = Q @ K^T (2-term), two-pass per kt ----
            float s4[8][4];
#pragma unroll
            for (int i = 0; i < 8; i++)
#pragma unroll
                for (int j = 0; j < 4; j++) s4[i][j] = 0.f;

#pragma unroll
            for (int kt = 0; kt < 4; kt++) {
                uint32_t kf[4][4];
#pragma unroll
                for (int np = 0; np < 4; np++) {
                    uint32_t boff = SWZ128((uint32_t)((np * 16 + lrow) * 128 + (kt * 16 + lcol) * 2));
                    ldm_x4(kf[np][0], kf[np][1], kf[np][2], kf[np][3], sKh + boff);
                }
#pragma unroll
                for (int np = 0; np < 4; np++) {
                    mma_f16(s4[np * 2],     qh[kt][0], qh[kt][1], qh[kt][2], qh[kt][3],
                            kf[np][0], kf[np][2]);
                    mma_f16(s4[np * 2 + 1], qh[kt][0], qh[kt][1], qh[kt][2], qh[kt][3],
                            kf[np][1], kf[np][3]);
                }
#pragma unroll
                for (int np = 0; np < 4; np++) {
                    mma_f16(s4[np * 2],     ql[kt][0], ql[kt][1], ql[kt][2], ql[kt][3],
                            kf[np][0], kf[np][2]);
                    mma_f16(s4[np * 2 + 1], ql[kt][0], ql[kt][1], ql[kt][2], ql[kt][3],
                            kf[np][1], kf[np][3]);
                }
            }

            // ---- scale + emphasis + causal mask ----
#pragma unroll
            for (int ni = 0; ni < 8; ni++)
#pragma unroll
                for (int e = 0; e < 4; e++) s4[ni][e] *= 0.125f;
            if (it == 0 && tig == 0) { s4[0][0] += 1.0f; s4[0][2] += 1.0f; }
            const int grow0 = q0 + wid * 16 + gid;
            const int grow1 = grow0 + 8;
            if (k0 + 63 > q0 + wid * 16) {
#pragma unroll
                for (int ni = 0; ni < 8; ni++) {
                    int gc = k0 + ni * 8 + tig * 2;
                    if (gc > grow0)     s4[ni][0] = -1e30f;
                    if (gc + 1 > grow0) s4[ni][1] = -1e30f;
                    if (gc > grow1)     s4[ni][2] = -1e30f;
                    if (gc + 1 > grow1) s4[ni][3] = -1e30f;
                }
            }

            // ---- online softmax ----
            float mx0 = s4[0][0], mx1 = s4[0][2];
#pragma unroll
            for (int ni = 0; ni < 8; ni++) {
                mx0 = fmaxf(mx0, fmaxf(s4[ni][0], s4[ni][1]));
                mx1 = fmaxf(mx1, fmaxf(s4[ni][2], s4[ni][3]));
            }
            mx0 = fmaxf(mx0, __shfl_xor_sync(0xffffffffu, mx0, 1));
            mx0 = fmaxf(mx0, __shfl_xor_sync(0xffffffffu, mx0, 2));
            mx1 = fmaxf(mx1, __shfl_xor_sync(0xffffffffu, mx1, 1));
            mx1 = fmaxf(mx1, __shfl_xor_sync(0xffffffffu, mx1, 2));
            float mn0 = fmaxf(m0r, mx0), mn1 = fmaxf(m1r, mx1);
            float a0 = __expf(m0r - mn0), a1 = __expf(m1r - mn1);
            m0r = mn0; m1r = mn1;
            float sum0 = 0.f, sum1 = 0.f;
#pragma unroll
            for (int ni = 0; ni < 8; ni++) {
                s4[ni][0] = __expf(s4[ni][0] - mn0);
                s4[ni][1] = __expf(s4[ni][1] - mn0);
                s4[ni][2] = __expf(s4[ni][2] - mn1);
                s4[ni][3] = __expf(s4[ni][3] - mn1);
                sum0 += s4[ni][0] + s4[ni][1];
                sum1 += s4[ni][2] + s4[ni][3];
            }
            sum0 += __shfl_xor_sync(0xffffffffu, sum0, 1);
            sum0 += __shfl_xor_sync(0xffffffffu, sum0, 2);
            sum1 += __shfl_xor_sync(0xffffffffu, sum1, 1);
            sum1 += __shfl_xor_sync(0xffffffffu, sum1, 2);
            l0r = l0r * a0 + sum0;
            l1r = l1r * a1 + sum1;

#pragma unroll
            for (int ni = 0; ni < 8; ni++) {
                o[ni][0] *= a0; o[ni][1] *= a0;
                o[ni][2] *= a1; o[ni][3] *= a1;
            }

            // ---- PV (2-term), two-pass per kt ----
#pragma unroll
            for (int kt = 0; kt < 4; kt++) {
                uint32_t ph[4], pl[4];
                {
                    float v0 = s4[2 * kt][0], v1 = s4[2 * kt][1];
                    float v2 = s4[2 * kt][2], v3 = s4[2 * kt][3];
                    float w0 = s4[2 * kt + 1][0], w1 = s4[2 * kt + 1][1];
                    float w2 = s4[2 * kt + 1][2], w3 = s4[2 * kt + 1][3];
                    ph[0] = pack_f16(v0, v1); ph[1] = pack_f16(v2, v3);
                    ph[2] = pack_f16(w0, w1); ph[3] = pack_f16(w2, w3);
                    pl[0] = pack_f16(f16_residual(v0), f16_residual(v1));
                    pl[1] = pack_f16(f16_residual(v2), f16_residual(v3));
                    pl[2] = pack_f16(f16_residual(w0), f16_residual(w1));
                    pl[3] = pack_f16(f16_residual(w2), f16_residual(w3));
                }
                uint32_t vf[4][4];
#pragma unroll
                for (int dp = 0; dp < 4; dp++) {
                    uint32_t voff = SWZ128((uint32_t)((kt * 16 + lrow) * 128 + (dp * 16 + lcol) * 2));
                    ldm_x4_t(vf[dp][0], vf[dp][1], vf[dp][2], vf[dp][3], sVh + voff);
                }
#pragma unroll
                for (int dp = 0; dp < 4; dp++) {
                    mma_f16(o[dp * 2],     ph[0], ph[1], ph[2], ph[3], vf[dp][0], vf[dp][1]);
                    mma_f16(o[dp * 2 + 1], ph[0], ph[1], ph[2], ph[3], vf[dp][2], vf[dp][3]);
                }
#pragma unroll
                for (int dp = 0; dp < 4; dp++) {
                    mma_f16(o[dp * 2],     pl[0], pl[1], pl[2], pl[3], vf[dp][0], vf[dp][1]);
                    mma_f16(o[dp * 2 + 1], pl[0], pl[1], pl[2], pl[3], vf[dp][2], vf[dp][3]);
                }
            }
        }

        __syncthreads();               // all warps done reading stage s
        if (it + 2 < niters && tid == 0) issue_kv((it + 2) % AT_NSTG, it + 2);
    }

    // ---- epilogue ----
    const float inv0 = 1.f / l0r, inv1 = 1.f / l1r;
    const int grow0 = q0 + wid * 16 + gid;
    const size_t r0o = (size_t)(b * T_ + grow0) * C_;
    const size_t r1o = (size_t)(b * T_ + grow0 + 8) * C_;
#pragma unroll
    for (int ni = 0; ni < 8; ni++) {
        int col = h * HD_ + ni * 8 + tig * 2;
        float v0 = o[ni][0] * inv0, v1 = o[ni][1] * inv0;
        float v2 = o[ni][2] * inv1, v3 = o[ni][3] * inv1;
        *(uint32_t*)(ah + r0o + col) = pack_f16(v0, v1);
        *(uint32_t*)(al + r0o + col) = pack_f16(f16_residual(v0), f16_residual(v1));
        *(uint32_t*)(ah + r1o + col) = pack_f16(v2, v3);
        *(uint32_t*)(al + r1o + col) = pack_f16(f16_residual(v2), f16_residual(v3));
    }
}

// ---------------------------------------------------------------------------
// Host: tensormap construction via driver entry point
// ---------------------------------------------------------------------------
typedef CUresult (*EncodeTiledFn)(
    CUtensorMap*, CUtensorMapDataType, cuuint32_t, void*,
    const cuuint64_t*, const cuuint64_t*, const cuuint32_t*, const cuuint32_t*,
    CUtensorMapInterleave, CUtensorMapSwizzle, CUtensorMapL2promotion,
    CUtensorMapFloatOOBfill);

static void make_map2d(EncodeTiledFn fn, CUtensorMap* m, void* base, int rows, int cols,
                       int boxy) {
    cuuint64_t dims[2]    = {(cuuint64_t)cols, (cuuint64_t)rows};
    cuuint64_t strides[1] = {(cuuint64_t)cols * 2};
    cuuint32_t box[2]     = {64, (cuuint32_t)boxy};   // 64 halfs = 128B rows (SW128)
    cuuint32_t estr[2]    = {1, 1};
    fn(m, CU_TENSOR_MAP_DATA_TYPE_FLOAT16, 2, base, dims, strides, box, estr,
       CU_TENSOR_MAP_INTERLEAVE_NONE, CU_TENSOR_MAP_SWIZZLE_128B,
       CU_TENSOR_MAP_L2_PROMOTION_L2_128B, CU_TENSOR_MAP_FLOAT_OOB_FILL_NONE);
}

extern "C" void kernel_launch(void* const* d_in, const int* in_sizes, int n_in,
                              void* d_out, int out_size)
{
    const float* x  = (const float*)d_in[0];
    const float* Wa = (const float*)d_in[1];
    const float* Wp = (const float*)d_in[2];
    float* y = (float*)d_out;

    __half *qkvh, *qkvl, *xh, *xl, *wah, *wph, *ah, *al;
    cudaGetSymbolAddress((void**)&qkvh, g_qkvh);
    cudaGetSymbolAddress((void**)&qkvl, g_qkvl);
    cudaGetSymbolAddress((void**)&xh, g_xh);
    cudaGetSymbolAddress((void**)&xl, g_xl);
    cudaGetSymbolAddress((void**)&wah, g_wah);
    cudaGetSymbolAddress((void**)&wph, g_wph);
    cudaGetSymbolAddress((void**)&ah, g_ah);
    cudaGetSymbolAddress((void**)&al, g_al);

    EncodeTiledFn enc = nullptr;
    cudaDriverEntryPointQueryResult qr;
#if CUDART_VERSION >= 12050
    cudaGetDriverEntryPointByVersion("cuTensorMapEncodeTiled", (void**)&enc, 12000,
                                     cudaEnableDefault, &qr);
#else
    cudaGetDriverEntryPoint("cuTensorMapEncodeTiled", (void**)&enc,
                            cudaEnableDefault, &qr);
#endif

    CUtensorMap m_xh, m_xl, m_wa, m_ah, m_al, m_wp, m_qh, m_ql, m_kv;
    make_map2d(enc, &m_xh, xh,  M_ROWS, C_, 128);
    make_map2d(enc, &m_xl, xl,  M_ROWS, C_, 128);
    make_map2d(enc, &m_wa, wah, C3_,    C_, 128);
    make_map2d(enc, &m_ah, ah,  M_ROWS, C_, 128);
    make_map2d(enc, &m_al, al,  M_ROWS, C_, 128);
    make_map2d(enc, &m_wp, wph, C_,     C_, 128);
    make_map2d(enc, &m_qh, qkvh, M_ROWS, C3_, 128);
    make_map2d(enc, &m_ql, qkvl, M_ROWS, C3_, 128);
    make_map2d(enc, &m_kv, qkvh, M_ROWS, C3_, 64);

    cudaFuncSetAttribute(gemm_tma_kernel<true>,
                         cudaFuncAttributeMaxDynamicSharedMemorySize, SMEM_GEMM);
    cudaFuncSetAttribute(gemm_tma_kernel<false>,
                         cudaFuncAttributeMaxDynamicSharedMemorySize, SMEM_GEMM);
    cudaFuncSetAttribute(attn_mma_kernel,
                         cudaFuncAttributeMaxDynamicSharedMemorySize, SMEM_ATTN);

    // 1) splits / weight transposes
    {
        int n4 = M_ROWS * C_ / 4;
        split_kernel<<<(n4 + 255) / 256, 256>>>(x, xh, xl, n4);
        dim3 grid_a(C3_ / 32, C_ / 32);
        transpose_f16_kernel<<<grid_a, dim3(32, 8)>>>(Wa, wah, C_, C3_);
        dim3 grid_p(C_ / 32, C_ / 32);
        transpose_f16_kernel<<<grid_p, dim3(32, 8)>>>(Wp, wph, C_, C_);
    }

    // 2) qkv = x @ W_attn -> fp16 hi/lo
    {
        dim3 grid(C3_ / 128, M_ROWS / 128);
        gemm_tma_kernel<true><<<grid, 256, SMEM_GEMM>>>(
            m_xh, m_xl, m_wa, nullptr, qkvh, qkvl, M_ROWS, C3_, C_);
    }

    // 3) flash attention (TMA-fed) -> fp16 hi/lo
    {
        dim3 grid(T_ / 128, B_ * H_);
        attn_mma_kernel<<<grid, 256, SMEM_ATTN>>>(m_qh, m_ql, m_kv, ah, al);
    }

    // 4) y = att @ W_proj (fp32 out)
    {
        dim3 grid(C_ / 128, M_ROWS / 128);
        gemm_tma_kernel<false><<<grid, 256, SMEM_GEMM>>>(
            m_ah, m_al, m_wp, y, nullptr, nullptr, M_ROWS, C_, C_);
    }
}

// round 16
// speedup vs baseline: 1.3434x; 1.1441x over previous
#include <cuda_runtime.h>
#include <cuda.h>
#include <cuda_fp16.h>
#include <cstdint>

// Problem dims (fixed per reference)
#define B_  2
#define T_  2048
#define C_  1024
#define H_  16
#define HD_ 64
#define C3_ 3072
#define M_ROWS (B_ * T_)   // 4096

// ---------------------------------------------------------------------------
// Scratch (allocation-free rule: device globals)   fp16 2-term scheme
// ---------------------------------------------------------------------------
__device__ __half g_qkvh[M_ROWS * C3_];
__device__ __half g_qkvl[M_ROWS * C3_];   // only Q cols written/read
__device__ __half g_xh[M_ROWS * C_];
__device__ __half g_xl[M_ROWS * C_];
__device__ __half g_wah[C3_ * C_];        // W_attn^T fp16 [3072, 1024]
__device__ __half g_wph[C_ * C_];         // W_proj^T fp16 [1024, 1024]
__device__ __half g_ah[M_ROWS * C_];
__device__ __half g_al[M_ROWS * C_];

// ---------------------------------------------------------------------------
__device__ __forceinline__ uint32_t smem_u32(const void* p) {
    uint32_t a;
    asm("{ .reg .u64 t; cvta.to.shared.u64 t, %1; cvt.u32.u64 %0, t; }" : "=r"(a) : "l"(p));
    return a;
}
__device__ __forceinline__ void ldm_x4(uint32_t& r0, uint32_t& r1, uint32_t& r2, uint32_t& r3,
                                       uint32_t addr) {
    asm volatile("ldmatrix.sync.aligned.m8n8.x4.shared.b16 {%0,%1,%2,%3}, [%4];"
                 : "=r"(r0), "=r"(r1), "=r"(r2), "=r"(r3) : "r"(addr));
}
__device__ __forceinline__ void ldm_x4_t(uint32_t& r0, uint32_t& r1, uint32_t& r2, uint32_t& r3,
                                         uint32_t addr) {
    asm volatile("ldmatrix.sync.aligned.m8n8.x4.trans.shared.b16 {%0,%1,%2,%3}, [%4];"
                 : "=r"(r0), "=r"(r1), "=r"(r2), "=r"(r3) : "r"(addr));
}
__device__ __forceinline__ void mma_f16(float* c, uint32_t a0, uint32_t a1, uint32_t a2,
                                        uint32_t a3, uint32_t b0, uint32_t b1) {
    asm volatile(
        "mma.sync.aligned.m16n8k16.row.col.f32.f16.f16.f32 "
        "{%0,%1,%2,%3}, {%4,%5,%6,%7}, {%8,%9}, {%0,%1,%2,%3};"
        : "+f"(c[0]), "+f"(c[1]), "+f"(c[2]), "+f"(c[3])
        : "r"(a0), "r"(a1), "r"(a2), "r"(a3), "r"(b0), "r"(b1));
}
__device__ __forceinline__ uint32_t pack_f16(float lo_elem, float hi_elem) {
    __half2 t = __floats2half2_rn(lo_elem, hi_elem);
    return *(uint32_t*)&t;
}
__device__ __forceinline__ float f16_residual(float v) {
    return v - __half2float(__float2half(v));
}

// mbarrier + TMA (sm_90 baseline features)
#define MBAR_INIT(a, n) asm volatile("mbarrier.init.shared.b64 [%0], %1;" :: "r"(a), "r"(n) : "memory")
#define MBAR_EXPECT_TX(a, n) \
    asm volatile("mbarrier.arrive.expect_tx.shared.b64 _, [%0], %1;" :: "r"(a), "r"(n) : "memory")
#define MBAR_WAIT(a, ph) do {                                                       \
    uint32_t _m = (a), _p = (ph), _d;                                               \
    asm volatile("{\n\t.reg .pred p;\n\t"                                           \
        "mbarrier.try_wait.parity.acquire.cta.shared::cta.b64 p, [%1], %2;\n\t"     \
        "selp.b32 %0, 1, 0, p;\n\t}" : "=r"(_d) : "r"(_m), "r"(_p) : "memory");     \
    if (!_d) {                                                                      \
        asm volatile("{\n\t.reg .pred P1;\n\t"                                      \
            "WL_%=:\n\t"                                                            \
            "mbarrier.try_wait.parity.acquire.cta.shared::cta.b64 P1, [%0], %1, 0x989680;\n\t" \
            "@P1 bra.uni WD_%=;\n\t"                                                \
            "bra.uni WL_%=;\n\t"                                                    \
            "WD_%=:\n\t}" :: "r"(_m), "r"(_p) : "memory");                          \
    } } while (0)
#define TMA_LOAD_2D(saddr, mapp, cx, cy, mbar) \
    asm volatile("cp.async.bulk.tensor.2d.shared::cta.global.tile.mbarrier::complete_tx::bytes " \
        "[%0], [%1, {%2, %3}], [%4];" \
        :: "r"(saddr), "l"(mapp), "r"(cx), "r"(cy), "r"(mbar) : "memory")
#define SWZ128(o) ((o) ^ (((o) >> 3) & 0x70))

// ---------------------------------------------------------------------------
// Split fp32 -> (hi, lo) fp16
// ---------------------------------------------------------------------------
__global__ __launch_bounds__(256) void split_kernel(
    const float* __restrict__ in, __half* __restrict__ hi,
    __half* __restrict__ lo, int n4)
{
    int i = blockIdx.x * blockDim.x + threadIdx.x;
    if (i >= n4) return;
    float4 v = ((const float4*)in)[i];
    float h0 = __half2float(__float2half(v.x));
    float h1 = __half2float(__float2half(v.y));
    float h2 = __half2float(__float2half(v.z));
    float h3 = __half2float(__float2half(v.w));
    uint32_t* ph = (uint32_t*)hi + i * 2;
    uint32_t* pl = (uint32_t*)lo + i * 2;
    ph[0] = pack_f16(v.x, v.y);  ph[1] = pack_f16(v.z, v.w);
    pl[0] = pack_f16(v.x - h0, v.y - h1);
    pl[1] = pack_f16(v.z - h2, v.w - h3);
}

// Transpose + fp16 round: in [K,N] fp32 -> hiT [N,K] fp16
__global__ __launch_bounds__(256) void transpose_f16_kernel(
    const float* __restrict__ in, __half* __restrict__ hiT, int K, int N)
{
    __shared__ float t[32][33];
    int n0 = blockIdx.x * 32, k0 = blockIdx.y * 32;
    int tx = threadIdx.x, ty = threadIdx.y;   // 32 x 8
#pragma unroll
    for (int i = 0; i < 32; i += 8)
        t[ty + i][tx] = in[(size_t)(k0 + ty + i) * N + n0 + tx];
    __syncthreads();
#pragma unroll
    for (int i = 0; i < 32; i += 8) {
        size_t o = (size_t)(n0 + ty + i) * K + k0 + tx;
        hiT[o] = __float2half(t[tx][ty + i]);
    }
}

// ---------------------------------------------------------------------------
// fp16 GEMM, TMA-fed:  C[M,N] = (Ah [+ Al]) @ Bh^T
// NTERMS: 1 = Ah only (for K/V columns), 2 = Ah+Al.
// OUT: 0 = fp32 to Cm, 1 = hi/lo split to Ch/Cl, 2 = hi only to Ch.
// 128x128 tile, BK=64, SW128 rows, 2-stage mbarrier pipeline.
// ---------------------------------------------------------------------------
#define TM_BK 64
#define TM_TILE_B 16384
#define TM_NSTG 2

template <int NTERMS, int OUT>
__global__ __launch_bounds__(256, 2) void gemm_tma_kernel(
    const __grid_constant__ CUtensorMap tmAh,
    const __grid_constant__ CUtensorMap tmAl,
    const __grid_constant__ CUtensorMap tmBh,
    float* __restrict__ Cm, __half* __restrict__ Ch,
    __half* __restrict__ Cl, int M, int N, int K, int n_off)
{
    constexpr uint32_t STAGE_B = (NTERMS + 1) * TM_TILE_B;
    extern __shared__ char smem_raw[];
    __shared__ uint64_t mbar_s[TM_NSTG];
    const uint32_t sb = (smem_u32(smem_raw) + 1023u) & ~1023u;
    const uint32_t mb0 = smem_u32(&mbar_s[0]);
    const int tid = threadIdx.x;
    const int wid = tid >> 5, lane = tid & 31;
    const int warp_m = wid >> 1;
    const int warp_n = wid & 1;
    const int m0 = blockIdx.y * 128;
    const int n0 = blockIdx.x * 128 + n_off;

    if (tid == 0) {
        MBAR_INIT(mb0, 1);
        MBAR_INIT(mb0 + 8, 1);
    }
    __syncthreads();

    auto issue_stage = [&](int s, int ch) {
        uint32_t mb = mb0 + s * 8;
        uint32_t base = sb + s * STAGE_B;
        MBAR_EXPECT_TX(mb, STAGE_B);
        int cx = ch * TM_BK;
        TMA_LOAD_2D(base, (const void*)&tmAh, cx, m0, mb);
        if (NTERMS == 2) TMA_LOAD_2D(base + TM_TILE_B, (const void*)&tmAl, cx, m0, mb);
        TMA_LOAD_2D(base + NTERMS * TM_TILE_B, (const void*)&tmBh, cx, n0, mb);
    };

    float acc[2][8][4];
#pragma unroll
    for (int i = 0; i < 2; i++)
#pragma unroll
        for (int j = 0; j < 8; j++)
#pragma unroll
            for (int q = 0; q < 4; q++) acc[i][j][q] = 0.f;

    const int lrow = lane & 15;
    const int lcol = (lane >> 4) << 3;

    auto compute_stage = [&](int s) {
        uint32_t base = sb + s * STAGE_B;
        uint32_t sAh = base, sAl = base + TM_TILE_B;
        uint32_t sBh = base + NTERMS * TM_TILE_B;
#pragma unroll
        for (int ks = 0; ks < 4; ks++) {
            const int kb = (ks * 16 + lcol) * 2;
            uint32_t ahf[2][4], alf[2][4];
#pragma unroll
            for (int mi = 0; mi < 2; mi++) {
                int r = warp_m * 32 + mi * 16 + lrow;
                uint32_t off = SWZ128((uint32_t)(r * 128 + kb));
                ldm_x4(ahf[mi][0], ahf[mi][1], ahf[mi][2], ahf[mi][3], sAh + off);
                if (NTERMS == 2)
                    ldm_x4(alf[mi][0], alf[mi][1], alf[mi][2], alf[mi][3], sAl + off);
            }
            uint32_t bf[4][4];
#pragma unroll
            for (int nt = 0; nt < 4; nt++) {
                int r = warp_n * 64 + nt * 16 + lrow;
                uint32_t off = SWZ128((uint32_t)(r * 128 + kb));
                ldm_x4(bf[nt][0], bf[nt][1], bf[nt][2], bf[nt][3], sBh + off);
            }
#pragma unroll
            for (int nt = 0; nt < 4; nt++)
#pragma unroll
                for (int mi = 0; mi < 2; mi++) {
                    mma_f16(acc[mi][nt * 2],     ahf[mi][0], ahf[mi][1], ahf[mi][2], ahf[mi][3],
                            bf[nt][0], bf[nt][2]);
                    mma_f16(acc[mi][nt * 2 + 1], ahf[mi][0], ahf[mi][1], ahf[mi][2], ahf[mi][3],
                            bf[nt][1], bf[nt][3]);
                }
            if (NTERMS == 2) {
#pragma unroll
                for (int nt = 0; nt < 4; nt++)
#pragma unroll
                    for (int mi = 0; mi < 2; mi++) {
                        mma_f16(acc[mi][nt * 2],     alf[mi][0], alf[mi][1], alf[mi][2], alf[mi][3],
                                bf[nt][0], bf[nt][2]);
                        mma_f16(acc[mi][nt * 2 + 1], alf[mi][0], alf[mi][1], alf[mi][2], alf[mi][3],
                                bf[nt][1], bf[nt][3]);
                    }
            }
        }
    };

    const int nch = K / TM_BK;
    if (tid == 0) {
        issue_stage(0, 0);
        issue_stage(1, 1);
    }
    int phase[TM_NSTG] = {0, 0};
    for (int ch = 0; ch < nch; ch++) {
        const int s = ch & 1;
        MBAR_WAIT(mb0 + s * 8, phase[s]);
        phase[s] ^= 1;
        compute_stage(s);
        __syncthreads();
        if (ch + 2 < nch && tid == 0) issue_stage(s, ch + 2);
    }

    const int gid = lane >> 2;
    const int tig = lane & 3;
#pragma unroll
    for (int mi = 0; mi < 2; mi++) {
        int rbase = m0 + warp_m * 32 + mi * 16 + gid;
#pragma unroll
        for (int ni = 0; ni < 8; ni++) {
            int col = n0 + warp_n * 64 + ni * 8 + tig * 2;
            float v0 = acc[mi][ni][0], v1 = acc[mi][ni][1];
            float v2 = acc[mi][ni][2], v3 = acc[mi][ni][3];
            if (OUT == 1) {
                *(uint32_t*)(Ch + (size_t)rbase * N + col) = pack_f16(v0, v1);
                *(uint32_t*)(Cl + (size_t)rbase * N + col) =
                    pack_f16(f16_residual(v0), f16_residual(v1));
                *(uint32_t*)(Ch + (size_t)(rbase + 8) * N + col) = pack_f16(v2, v3);
                *(uint32_t*)(Cl + (size_t)(rbase + 8) * N + col) =
                    pack_f16(f16_residual(v2), f16_residual(v3));
            } else if (OUT == 2) {
                *(uint32_t*)(Ch + (size_t)rbase * N + col) = pack_f16(v0, v1);
                *(uint32_t*)(Ch + (size_t)(rbase + 8) * N + col) = pack_f16(v2, v3);
            } else {
                float* p0 = Cm + (size_t)rbase * N + col;
                float* p1 = Cm + (size_t)(rbase + 8) * N + col;
                p0[0] = v0; p0[1] = v1;
                p1[0] = v2; p1[1] = v3;
            }
        }
    }
}

// ---------------------------------------------------------------------------
// fp16 2-term flash attention, TMA-fed (unchanged from round 15 known-good)
// ---------------------------------------------------------------------------
#define AQ_TILE 16384
#define AKV_TILE 8192
#define AKV_STG (2 * AKV_TILE)
#define AT_NSTG 3
#define SMEM_ATTN (2 * AQ_TILE + AT_NSTG * AKV_STG + 1024)   // 82944

__global__ __launch_bounds__(256, 1) void attn_mma_kernel(
    const __grid_constant__ CUtensorMap tmQh,
    const __grid_constant__ CUtensorMap tmQl,
    const __grid_constant__ CUtensorMap tmKV,
    __half* __restrict__ ah, __half* __restrict__ al)
{
    extern __shared__ char smem_raw[];
    __shared__ uint64_t mbar_s[1 + AT_NSTG];
    const uint32_t sb = (smem_u32(smem_raw) + 1023u) & ~1023u;
    const uint32_t mbQ = smem_u32(&mbar_s[0]);
    const uint32_t mbKV = mbQ + 8;
    const int tid = threadIdx.x;
    const int wid = tid >> 5, lane = tid & 31;
    const int qt = (int)gridDim.x - 1 - (int)blockIdx.x;
    const int bh = blockIdx.y;
    const int b = bh >> 4, h = bh & 15;
    const int q0 = qt * 128;

    const uint32_t sQh = sb, sQl = sb + AQ_TILE;
    const uint32_t stg0 = sb + 2 * AQ_TILE;
    const int niters = 2 * qt + 2;

    if (tid == 0) {
        MBAR_INIT(mbQ, 1);
#pragma unroll
        for (int s = 0; s < AT_NSTG; s++) MBAR_INIT(mbKV + s * 8, 1);
    }
    __syncthreads();

    auto issue_kv = [&](int s, int it) {
        uint32_t mb = mbKV + s * 8;
        uint32_t base = stg0 + s * AKV_STG;
        MBAR_EXPECT_TX(mb, AKV_STG);
        int cy = b * T_ + it * 64;
        TMA_LOAD_2D(base,            (const void*)&tmKV, C_ + h * HD_,     cy, mb);
        TMA_LOAD_2D(base + AKV_TILE, (const void*)&tmKV, 2 * C_ + h * HD_, cy, mb);
    };

    if (tid == 0) {
        MBAR_EXPECT_TX(mbQ, 2 * AQ_TILE);
        TMA_LOAD_2D(sQh, (const void*)&tmQh, h * HD_, b * T_ + q0, mbQ);
        TMA_LOAD_2D(sQl, (const void*)&tmQl, h * HD_, b * T_ + q0, mbQ);
        issue_kv(0, 0);
        issue_kv(1, 1);
    }

    const int lrow = lane & 15;
    const int lcol = (lane >> 4) << 3;
    const int gid = lane >> 2;
    const int tig = lane & 3;

    MBAR_WAIT(mbQ, 0);

    uint32_t qh[4][4], ql[4][4];
#pragma unroll
    for (int kt = 0; kt < 4; kt++) {
        uint32_t off = SWZ128((uint32_t)((wid * 16 + lrow) * 128 + (kt * 16 + lcol) * 2));
        ldm_x4(qh[kt][0], qh[kt][1], qh[kt][2], qh[kt][3], sQh + off);
        ldm_x4(ql[kt][0], ql[kt][1], ql[kt][2], ql[kt][3], sQl + off);
    }

    float o[8][4];
#pragma unroll
    for (int i = 0; i < 8; i++)
#pragma unroll
        for (int j = 0; j < 4; j++) o[i][j] = 0.f;
    float m0r = -1e30f, m1r = -1e30f, l0r = 0.f, l1r = 0.f;

    for (int it = 0; it < niters; it++) {
        const int s = it % AT_NSTG;
        MBAR_WAIT(mbKV + s * 8, (it / AT_NSTG) & 1);

        const uint32_t sKh = stg0 + s * AKV_STG;
        const uint32_t sVh = sKh + AKV_TILE;
        const int k0 = it * 64;
        const bool active = (q0 + wid * 16 + 15 >= k0);

        if (active) {
            float s4[8][4];
#pragma unroll
            for (int i = 0; i < 8; i++)
#pragma unroll
                for (int j = 0; j < 4; j++) s4[i][j] = 0.f;

#pragma unroll
            for (int kt = 0; kt < 4; kt++) {
                uint32_t kf[4][4];
#pragma unroll
                for (int np = 0; np < 4; np++) {
                    uint32_t boff = SWZ128((uint32_t)((np * 16 + lrow) * 128 + (kt * 16 + lcol) * 2));
                    ldm_x4(kf[np][0], kf[np][1], kf[np][2], kf[np][3], sKh + boff);
                }
#pragma unroll
                for (int np = 0; np < 4; np++) {
                    mma_f16(s4[np * 2],     qh[kt][0], qh[kt][1], qh[kt][2], qh[kt][3],
                            kf[np][0], kf[np][2]);
                    mma_f16(s4[np * 2 + 1], qh[kt][0], qh[kt][1], qh[kt][2], qh[kt][3],
                            kf[np][1], kf[np][3]);
                }
#pragma unroll
                for (int np = 0; np < 4; np++) {
                    mma_f16(s4[np * 2],     ql[kt][0], ql[kt][1], ql[kt][2], ql[kt][3],
                            kf[np][0], kf[np][2]);
                    mma_f16(s4[np * 2 + 1], ql[kt][0], ql[kt][1], ql[kt][2], ql[kt][3],
                            kf[np][1], kf[np][3]);
                }
            }

#pragma unroll
            for (int ni = 0; ni < 8; ni++)
#pragma unroll
                for (int e = 0; e < 4; e++) s4[ni][e] *= 0.125f;
            if (it == 0 && tig == 0) { s4[0][0] += 1.0f; s4[0][2] += 1.0f; }
            const int grow0 = q0 + wid * 16 + gid;
            const int grow1 = grow0 + 8;
            if (k0 + 63 > q0 + wid * 16) {
#pragma unroll
                for (int ni = 0; ni < 8; ni++) {
                    int gc = k0 + ni * 8 + tig * 2;
                    if (gc > grow0)     s4[ni][0] = -1e30f;
                    if (gc + 1 > grow0) s4[ni][1] = -1e30f;
                    if (gc > grow1)     s4[ni][2] = -1e30f;
                    if (gc + 1 > grow1) s4[ni][3] = -1e30f;
                }
            }

            float mx0 = s4[0][0], mx1 = s4[0][2];
#pragma unroll
            for (int ni = 0; ni < 8; ni++) {
                mx0 = fmaxf(mx0, fmaxf(s4[ni][0], s4[ni][1]));
                mx1 = fmaxf(mx1, fmaxf(s4[ni][2], s4[ni][3]));
            }
            mx0 = fmaxf(mx0, __shfl_xor_sync(0xffffffffu, mx0, 1));
            mx0 = fmaxf(mx0, __shfl_xor_sync(0xffffffffu, mx0, 2));
            mx1 = fmaxf(mx1, __shfl_xor_sync(0xffffffffu, mx1, 1));
            mx1 = fmaxf(mx1, __shfl_xor_sync(0xffffffffu, mx1, 2));
            float mn0 = fmaxf(m0r, mx0), mn1 = fmaxf(m1r, mx1);
            float a0 = __expf(m0r - mn0), a1 = __expf(m1r - mn1);
            m0r = mn0; m1r = mn1;
            float sum0 = 0.f, sum1 = 0.f;
#pragma unroll
            for (int ni = 0; ni < 8; ni++) {
                s4[ni][0] = __expf(s4[ni][0] - mn0);
                s4[ni][1] = __expf(s4[ni][1] - mn0);
                s4[ni][2] = __expf(s4[ni][2] - mn1);
                s4[ni][3] = __expf(s4[ni][3] - mn1);
                sum0 += s4[ni][0] + s4[ni][1];
                sum1 += s4[ni][2] + s4[ni][3];
            }
            sum0 += __shfl_xor_sync(0xffffffffu, sum0, 1);
            sum0 += __shfl_xor_sync(0xffffffffu, sum0, 2);
            sum1 += __shfl_xor_sync(0xffffffffu, sum1, 1);
            sum1 += __shfl_xor_sync(0xffffffffu, sum1, 2);
            l0r = l0r * a0 + sum0;
            l1r = l1r * a1 + sum1;

#pragma unroll
            for (int ni = 0; ni < 8; ni++) {
                o[ni][0] *= a0; o[ni][1] *= a0;
                o[ni][2] *= a1; o[ni][3] *= a1;
            }

#pragma unroll
            for (int kt = 0; kt < 4; kt++) {
                uint32_t ph[4], pl[4];
                {
                    float v0 = s4[2 * kt][0], v1 = s4[2 * kt][1];
                    float v2 = s4[2 * kt][2], v3 = s4[2 * kt][3];
                    float w0 = s4[2 * kt + 1][0], w1 = s4[2 * kt + 1][1];
                    float w2 = s4[2 * kt + 1][2], w3 = s4[2 * kt + 1][3];
                    ph[0] = pack_f16(v0, v1); ph[1] = pack_f16(v2, v3);
                    ph[2] = pack_f16(w0, w1); ph[3] = pack_f16(w2, w3);
                    pl[0] = pack_f16(f16_residual(v0), f16_residual(v1));
                    pl[1] = pack_f16(f16_residual(v2), f16_residual(v3));
                    pl[2] = pack_f16(f16_residual(w0), f16_residual(w1));
                    pl[3] = pack_f16(f16_residual(w2), f16_residual(w3));
                }
                uint32_t vf[4][4];
#pragma unroll
                for (int dp = 0; dp < 4; dp++) {
                    uint32_t voff = SWZ128((uint32_t)((kt * 16 + lrow) * 128 + (dp * 16 + lcol) * 2));
                    ldm_x4_t(vf[dp][0], vf[dp][1], vf[dp][2], vf[dp][3], sVh + voff);
                }
#pragma unroll
                for (int dp = 0; dp < 4; dp++) {
                    mma_f16(o[dp * 2],     ph[0], ph[1], ph[2], ph[3], vf[dp][0], vf[dp][1]);
                    mma_f16(o[dp * 2 + 1], ph[0], ph[1], ph[2], ph[3], vf[dp][2], vf[dp][3]);
                }
#pragma unroll
                for (int dp = 0; dp < 4; dp++) {
                    mma_f16(o[dp * 2],     pl[0], pl[1], pl[2], pl[3], vf[dp][0], vf[dp][1]);
                    mma_f16(o[dp * 2 + 1], pl[0], pl[1], pl[2], pl[3], vf[dp][2], vf[dp][3]);
                }
            }
        }

        __syncthreads();
        if (it + 2 < niters && tid == 0) issue_kv((it + 2) % AT_NSTG, it + 2);
    }

    const float inv0 = 1.f / l0r, inv1 = 1.f / l1r;
    const int grow0 = q0 + wid * 16 + gid;
    const size_t r0o = (size_t)(b * T_ + grow0) * C_;
    const size_t r1o = (size_t)(b * T_ + grow0 + 8) * C_;
#pragma unroll
    for (int ni = 0; ni < 8; ni++) {
        int col = h * HD_ + ni * 8 + tig * 2;
        float v0 = o[ni][0] * inv0, v1 = o[ni][1] * inv0;
        float v2 = o[ni][2] * inv1, v3 = o[ni][3] * inv1;
        *(uint32_t*)(ah + r0o + col) = pack_f16(v0, v1);
        *(uint32_t*)(al + r0o + col) = pack_f16(f16_residual(v0), f16_residual(v1));
        *(uint32_t*)(ah + r1o + col) = pack_f16(v2, v3);
        *(uint32_t*)(al + r1o + col) = pack_f16(f16_residual(v2), f16_residual(v3));
    }
}

// ---------------------------------------------------------------------------
// Host: tensormap construction via driver entry point
// ---------------------------------------------------------------------------
typedef CUresult (*EncodeTiledFn)(
    CUtensorMap*, CUtensorMapDataType, cuuint32_t, void*,
    const cuuint64_t*, const cuuint64_t*, const cuuint32_t*, const cuuint32_t*,
    CUtensorMapInterleave, CUtensorMapSwizzle, CUtensorMapL2promotion,
    CUtensorMapFloatOOBfill);

static void make_map2d(EncodeTiledFn fn, CUtensorMap* m, void* base, int rows, int cols,
                       int boxy) {
    cuuint64_t dims[2]    = {(cuuint64_t)cols, (cuuint64_t)rows};
    cuuint64_t strides[1] = {(cuuint64_t)cols * 2};
    cuuint32_t box[2]     = {64, (cuuint32_t)boxy};
    cuuint32_t estr[2]    = {1, 1};
    fn(m, CU_TENSOR_MAP_DATA_TYPE_FLOAT16, 2, base, dims, strides, box, estr,
       CU_TENSOR_MAP_INTERLEAVE_NONE, CU_TENSOR_MAP_SWIZZLE_128B,
       CU_TENSOR_MAP_L2_PROMOTION_L2_128B, CU_TENSOR_MAP_FLOAT_OOB_FILL_NONE);
}

extern "C" void kernel_launch(void* const* d_in, const int* in_sizes, int n_in,
                              void* d_out, int out_size)
{
    const float* x  = (const float*)d_in[0];
    const float* Wa = (const float*)d_in[1];
    const float* Wp = (const float*)d_in[2];
    float* y = (float*)d_out;

    __half *qkvh, *qkvl, *xh, *xl, *wah, *wph, *ah, *al;
    cudaGetSymbolAddress((void**)&qkvh, g_qkvh);
    cudaGetSymbolAddress((void**)&qkvl, g_qkvl);
    cudaGetSymbolAddress((void**)&xh, g_xh);
    cudaGetSymbolAddress((void**)&xl, g_xl);
    cudaGetSymbolAddress((void**)&wah, g_wah);
    cudaGetSymbolAddress((void**)&wph, g_wph);
    cudaGetSymbolAddress((void**)&ah, g_ah);
    cudaGetSymbolAddress((void**)&al, g_al);

    EncodeTiledFn enc = nullptr;
    cudaDriverEntryPointQueryResult qr;
#if CUDART_VERSION >= 12050
    cudaGetDriverEntryPointByVersion("cuTensorMapEncodeTiled", (void**)&enc, 12000,
                                     cudaEnableDefault, &qr);
#else
    cudaGetDriverEntryPoint("cuTensorMapEncodeTiled", (void**)&enc,
                            cudaEnableDefault, &qr);
#endif

    CUtensorMap m_xh, m_xl, m_wa, m_ah, m_al, m_wp, m_qh, m_ql, m_kv;
    make_map2d(enc, &m_xh, xh,  M_ROWS, C_, 128);
    make_map2d(enc, &m_xl, xl,  M_ROWS, C_, 128);
    make_map2d(enc, &m_wa, wah, C3_,    C_, 128);
    make_map2d(enc, &m_ah, ah,  M_ROWS, C_, 128);
    make_map2d(enc, &m_al, al,  M_ROWS, C_, 128);
    make_map2d(enc, &m_wp, wph, C_,     C_, 128);
    make_map2d(enc, &m_qh, qkvh, M_ROWS, C3_, 128);
    make_map2d(enc, &m_ql, qkvl, M_ROWS, C3_, 128);
    make_map2d(enc, &m_kv, qkvh, M_ROWS, C3_, 64);

    const int SM_G2 = 2 * 3 * TM_TILE_B + 1024;   // 2-term stages
    const int SM_G1 = 2 * 2 * TM_TILE_B + 1024;   // 1-term stages
    cudaFuncSetAttribute(gemm_tma_kernel<2, 1>,
                         cudaFuncAttributeMaxDynamicSharedMemorySize, SM_G2);
    cudaFuncSetAttribute(gemm_tma_kernel<1, 2>,
                         cudaFuncAttributeMaxDynamicSharedMemorySize, SM_G1);
    cudaFuncSetAttribute(gemm_tma_kernel<2, 0>,
                         cudaFuncAttributeMaxDynamicSharedMemorySize, SM_G2);
    cudaFuncSetAttribute(attn_mma_kernel,
                         cudaFuncAttributeMaxDynamicSharedMemorySize, SMEM_ATTN);

    // 1) splits / weight transposes
    {
        int n4 = M_ROWS * C_ / 4;
        split_kernel<<<(n4 + 255) / 256, 256>>>(x, xh, xl, n4);
        dim3 grid_a(C3_ / 32, C_ / 32);
        transpose_f16_kernel<<<grid_a, dim3(32, 8)>>>(Wa, wah, C_, C3_);
        dim3 grid_p(C_ / 32, C_ / 32);
        transpose_f16_kernel<<<grid_p, dim3(32, 8)>>>(Wp, wph, C_, C_);
    }

    // 2a) Q columns: 2-term, hi/lo split out  (cols 0..1023)
    {
        dim3 grid(C_ / 128, M_ROWS / 128);
        gemm_tma_kernel<2, 1><<<grid, 256, SM_G2>>>(
            m_xh, m_xl, m_wa, nullptr, qkvh, qkvl, M_ROWS, C3_, C_, 0);
    }
    // 2b) K/V columns: 1-term, hi only  (cols 1024..3071)
    {
        dim3 grid(2 * C_ / 128, M_ROWS / 128);
        gemm_tma_kernel<1, 2><<<grid, 256, SM_G1>>>(
            m_xh, m_xl, m_wa, nullptr, qkvh, nullptr, M_ROWS, C3_, C_, C_);
    }

    // 3) flash attention (TMA-fed) -> fp16 hi/lo
    {
        dim3 grid(T_ / 128, B_ * H_);
        attn_mma_kernel<<<grid, 256, SMEM_ATTN>>>(m_qh, m_ql, m_kv, ah, al);
    }

    // 4) y = att @ W_proj (fp32 out, 2-term)
    {
        dim3 grid(C_ / 128, M_ROWS / 128);
        gemm_tma_kernel<2, 0><<<grid, 256, SM_G2>>>(
            m_ah, m_al, m_wp, y, nullptr, nullptr, M_ROWS, C_, C_, 0);
    }
}

// round 17
// speedup vs baseline: 1.4290x; 1.0637x over previous
#include <cuda_runtime.h>
#include <cuda.h>
#include <cuda_fp16.h>
#include <cstdint>

// Problem dims (fixed per reference)
#define B_  2
#define T_  2048
#define C_  1024
#define H_  16
#define HD_ 64
#define C3_ 3072
#define M_ROWS (B_ * T_)   // 4096

// ---------------------------------------------------------------------------
// Scratch (allocation-free rule: device globals)
// ---------------------------------------------------------------------------
__device__ __half g_qkvh[M_ROWS * C3_];
__device__ __half g_qkvl[M_ROWS * C3_];   // only Q cols written/read
__device__ __half g_xh[M_ROWS * C_];
__device__ __half g_xl[M_ROWS * C_];
__device__ __half g_wah[C3_ * C_];        // W_attn^T fp16 [3072, 1024]
__device__ __half g_wph[C_ * C_];         // W_proj^T fp16 [1024, 1024]
__device__ __half g_ah[M_ROWS * C_];

// ---------------------------------------------------------------------------
__device__ __forceinline__ uint32_t smem_u32(const void* p) {
    uint32_t a;
    asm("{ .reg .u64 t; cvta.to.shared.u64 t, %1; cvt.u32.u64 %0, t; }" : "=r"(a) : "l"(p));
    return a;
}
__device__ __forceinline__ void ldm_x4(uint32_t& r0, uint32_t& r1, uint32_t& r2, uint32_t& r3,
                                       uint32_t addr) {
    asm volatile("ldmatrix.sync.aligned.m8n8.x4.shared.b16 {%0,%1,%2,%3}, [%4];"
                 : "=r"(r0), "=r"(r1), "=r"(r2), "=r"(r3) : "r"(addr));
}
__device__ __forceinline__ void ldm_x4_t(uint32_t& r0, uint32_t& r1, uint32_t& r2, uint32_t& r3,
                                         uint32_t addr) {
    asm volatile("ldmatrix.sync.aligned.m8n8.x4.trans.shared.b16 {%0,%1,%2,%3}, [%4];"
                 : "=r"(r0), "=r"(r1), "=r"(r2), "=r"(r3) : "r"(addr));
}
__device__ __forceinline__ void mma_f16(float* c, uint32_t a0, uint32_t a1, uint32_t a2,
                                        uint32_t a3, uint32_t b0, uint32_t b1) {
    asm volatile(
        "mma.sync.aligned.m16n8k16.row.col.f32.f16.f16.f32 "
        "{%0,%1,%2,%3}, {%4,%5,%6,%7}, {%8,%9}, {%0,%1,%2,%3};"
        : "+f"(c[0]), "+f"(c[1]), "+f"(c[2]), "+f"(c[3])
        : "r"(a0), "r"(a1), "r"(a2), "r"(a3), "r"(b0), "r"(b1));
}
__device__ __forceinline__ uint32_t pack_f16(float lo_elem, float hi_elem) {
    __half2 t = __floats2half2_rn(lo_elem, hi_elem);
    return *(uint32_t*)&t;
}
__device__ __forceinline__ float f16_residual(float v) {
    return v - __half2float(__float2half(v));
}

// mbarrier + TMA (sm_90 baseline features)
#define MBAR_INIT(a, n) asm volatile("mbarrier.init.shared.b64 [%0], %1;" :: "r"(a), "r"(n) : "memory")
#define MBAR_EXPECT_TX(a, n) \
    asm volatile("mbarrier.arrive.expect_tx.shared.b64 _, [%0], %1;" :: "r"(a), "r"(n) : "memory")
#define MBAR_WAIT(a, ph) do {                                                       \
    uint32_t _m = (a), _p = (ph), _d;                                               \
    asm volatile("{\n\t.reg .pred p;\n\t"                                           \
        "mbarrier.try_wait.parity.acquire.cta.shared::cta.b64 p, [%1], %2;\n\t"     \
        "selp.b32 %0, 1, 0, p;\n\t}" : "=r"(_d) : "r"(_m), "r"(_p) : "memory");     \
    if (!_d) {                                                                      \
        asm volatile("{\n\t.reg .pred P1;\n\t"                                      \
            "WL_%=:\n\t"                                                            \
            "mbarrier.try_wait.parity.acquire.cta.shared::cta.b64 P1, [%0], %1, 0x989680;\n\t" \
            "@P1 bra.uni WD_%=;\n\t"                                                \
            "bra.uni WL_%=;\n\t"                                                    \
            "WD_%=:\n\t}" :: "r"(_m), "r"(_p) : "memory");                          \
    } } while (0)
#define TMA_LOAD_2D(saddr, mapp, cx, cy, mbar) \
    asm volatile("cp.async.bulk.tensor.2d.shared::cta.global.tile.mbarrier::complete_tx::bytes " \
        "[%0], [%1, {%2, %3}], [%4];" \
        :: "r"(saddr), "l"(mapp), "r"(cx), "r"(cy), "r"(mbar) : "memory")
#define SWZ128(o) ((o) ^ (((o) >> 3) & 0x70))

// ---------------------------------------------------------------------------
// Split fp32 -> (hi, lo) fp16
// ---------------------------------------------------------------------------
__global__ __launch_bounds__(256) void split_kernel(
    const float* __restrict__ in, __half* __restrict__ hi,
    __half* __restrict__ lo, int n4)
{
    int i = blockIdx.x * blockDim.x + threadIdx.x;
    if (i >= n4) return;
    float4 v = ((const float4*)in)[i];
    float h0 = __half2float(__float2half(v.x));
    float h1 = __half2float(__float2half(v.y));
    float h2 = __half2float(__float2half(v.z));
    float h3 = __half2float(__float2half(v.w));
    uint32_t* ph = (uint32_t*)hi + i * 2;
    uint32_t* pl = (uint32_t*)lo + i * 2;
    ph[0] = pack_f16(v.x, v.y);  ph[1] = pack_f16(v.z, v.w);
    pl[0] = pack_f16(v.x - h0, v.y - h1);
    pl[1] = pack_f16(v.z - h2, v.w - h3);
}

// Transpose + fp16 round: in [K,N] fp32 -> hiT [N,K] fp16
__global__ __launch_bounds__(256) void transpose_f16_kernel(
    const float* __restrict__ in, __half* __restrict__ hiT, int K, int N)
{
    __shared__ float t[32][33];
    int n0 = blockIdx.x * 32, k0 = blockIdx.y * 32;
    int tx = threadIdx.x, ty = threadIdx.y;   // 32 x 8
#pragma unroll
    for (int i = 0; i < 32; i += 8)
        t[ty + i][tx] = in[(size_t)(k0 + ty + i) * N + n0 + tx];
    __syncthreads();
#pragma unroll
    for (int i = 0; i < 32; i += 8) {
        size_t o = (size_t)(n0 + ty + i) * K + k0 + tx;
        hiT[o] = __float2half(t[tx][ty + i]);
    }
}

// ---------------------------------------------------------------------------
// Merged QKV GEMM, TMA-fed. Runtime branch per CTA:
//   n0 <  1024 (Q cols):  2-term (Ah+Al)@B, hi/lo split out
//   n0 >= 1024 (KV cols): 1-term Ah@B, hi only out
// 128x128 tile, BK=64, SW128 rows, 2-stage mbarrier pipe, 2 CTAs/SM.
// ---------------------------------------------------------------------------
#define TM_BK 64
#define TM_TILE_B 16384
#define TM_STAGE_B (3 * TM_TILE_B)
#define TM_NSTG 2
#define SMEM_QKV (TM_NSTG * TM_STAGE_B + 1024)

__global__ __launch_bounds__(256, 2) void gemm_qkv_kernel(
    const __grid_constant__ CUtensorMap tmAh,
    const __grid_constant__ CUtensorMap tmAl,
    const __grid_constant__ CUtensorMap tmBh,
    __half* __restrict__ Ch, __half* __restrict__ Cl, int M, int N, int K)
{
    extern __shared__ char smem_raw[];
    __shared__ uint64_t mbar_s[TM_NSTG];
    const uint32_t sb = (smem_u32(smem_raw) + 1023u) & ~1023u;
    const uint32_t mb0 = smem_u32(&mbar_s[0]);
    const int tid = threadIdx.x;
    const int wid = tid >> 5, lane = tid & 31;
    const int warp_m = wid >> 1;
    const int warp_n = wid & 1;
    const int m0 = blockIdx.y * 128;
    const int n0 = blockIdx.x * 128;
    const bool two = (n0 < C_);          // Q columns get 2-term

    if (tid == 0) {
        MBAR_INIT(mb0, 1);
        MBAR_INIT(mb0 + 8, 1);
    }
    __syncthreads();

    const uint32_t tx_bytes = two ? 3 * TM_TILE_B : 2 * TM_TILE_B;
    auto issue_stage = [&](int s, int ch) {
        uint32_t mb = mb0 + s * 8;
        uint32_t base = sb + s * TM_STAGE_B;
        MBAR_EXPECT_TX(mb, tx_bytes);
        int cx = ch * TM_BK;
        TMA_LOAD_2D(base, (const void*)&tmAh, cx, m0, mb);
        if (two) TMA_LOAD_2D(base + TM_TILE_B, (const void*)&tmAl, cx, m0, mb);
        TMA_LOAD_2D(base + 2 * TM_TILE_B, (const void*)&tmBh, cx, n0, mb);
    };

    float acc[2][8][4];
#pragma unroll
    for (int i = 0; i < 2; i++)
#pragma unroll
        for (int j = 0; j < 8; j++)
#pragma unroll
            for (int q = 0; q < 4; q++) acc[i][j][q] = 0.f;

    const int lrow = lane & 15;
    const int lcol = (lane >> 4) << 3;

    auto compute_stage = [&](int s) {
        uint32_t base = sb + s * TM_STAGE_B;
        uint32_t sAh = base, sAl = base + TM_TILE_B, sBh = base + 2 * TM_TILE_B;
#pragma unroll
        for (int ks = 0; ks < 4; ks++) {
            const int kb = (ks * 16 + lcol) * 2;
            uint32_t ahf[2][4], alf[2][4];
#pragma unroll
            for (int mi = 0; mi < 2; mi++) {
                int r = warp_m * 32 + mi * 16 + lrow;
                uint32_t off = SWZ128((uint32_t)(r * 128 + kb));
                ldm_x4(ahf[mi][0], ahf[mi][1], ahf[mi][2], ahf[mi][3], sAh + off);
                if (two)
                    ldm_x4(alf[mi][0], alf[mi][1], alf[mi][2], alf[mi][3], sAl + off);
            }
            uint32_t bf[4][4];
#pragma unroll
            for (int nt = 0; nt < 4; nt++) {
                int r = warp_n * 64 + nt * 16 + lrow;
                uint32_t off = SWZ128((uint32_t)(r * 128 + kb));
                ldm_x4(bf[nt][0], bf[nt][1], bf[nt][2], bf[nt][3], sBh + off);
            }
#pragma unroll
            for (int nt = 0; nt < 4; nt++)
#pragma unroll
                for (int mi = 0; mi < 2; mi++) {
                    mma_f16(acc[mi][nt * 2],     ahf[mi][0], ahf[mi][1], ahf[mi][2], ahf[mi][3],
                            bf[nt][0], bf[nt][2]);
                    mma_f16(acc[mi][nt * 2 + 1], ahf[mi][0], ahf[mi][1], ahf[mi][2], ahf[mi][3],
                            bf[nt][1], bf[nt][3]);
                }
            if (two) {
#pragma unroll
                for (int nt = 0; nt < 4; nt++)
#pragma unroll
                    for (int mi = 0; mi < 2; mi++) {
                        mma_f16(acc[mi][nt * 2],     alf[mi][0], alf[mi][1], alf[mi][2], alf[mi][3],
                                bf[nt][0], bf[nt][2]);
                        mma_f16(acc[mi][nt * 2 + 1], alf[mi][0], alf[mi][1], alf[mi][2], alf[mi][3],
                                bf[nt][1], bf[nt][3]);
                    }
            }
        }
    };

    const int nch = K / TM_BK;
    if (tid == 0) {
        issue_stage(0, 0);
        issue_stage(1, 1);
    }
    int phase[TM_NSTG] = {0, 0};
    for (int ch = 0; ch < nch; ch++) {
        const int s = ch & 1;
        MBAR_WAIT(mb0 + s * 8, phase[s]);
        phase[s] ^= 1;
        compute_stage(s);
        __syncthreads();
        if (ch + 2 < nch && tid == 0) issue_stage(s, ch + 2);
    }

    const int gid = lane >> 2;
    const int tig = lane & 3;
#pragma unroll
    for (int mi = 0; mi < 2; mi++) {
        int rbase = m0 + warp_m * 32 + mi * 16 + gid;
#pragma unroll
        for (int ni = 0; ni < 8; ni++) {
            int col = n0 + warp_n * 64 + ni * 8 + tig * 2;
            float v0 = acc[mi][ni][0], v1 = acc[mi][ni][1];
            float v2 = acc[mi][ni][2], v3 = acc[mi][ni][3];
            *(uint32_t*)(Ch + (size_t)rbase * N + col) = pack_f16(v0, v1);
            *(uint32_t*)(Ch + (size_t)(rbase + 8) * N + col) = pack_f16(v2, v3);
            if (two) {
                *(uint32_t*)(Cl + (size_t)rbase * N + col) =
                    pack_f16(f16_residual(v0), f16_residual(v1));
                *(uint32_t*)(Cl + (size_t)(rbase + 8) * N + col) =
                    pack_f16(f16_residual(v2), f16_residual(v3));
            }
        }
    }
}

// ---------------------------------------------------------------------------
// Projection GEMM (1-term): y[M,N] = Ah @ Bh^T, fp32 out.
// ---------------------------------------------------------------------------
#define PJ_STAGE_B (2 * TM_TILE_B)
#define SMEM_PROJ (TM_NSTG * PJ_STAGE_B + 1024)

__global__ __launch_bounds__(256, 2) void gemm_proj_kernel(
    const __grid_constant__ CUtensorMap tmAh,
    const __grid_constant__ CUtensorMap tmBh,
    float* __restrict__ Cm, int M, int N, int K)
{
    extern __shared__ char smem_raw[];
    __shared__ uint64_t mbar_s[TM_NSTG];
    const uint32_t sb = (smem_u32(smem_raw) + 1023u) & ~1023u;
    const uint32_t mb0 = smem_u32(&mbar_s[0]);
    const int tid = threadIdx.x;
    const int wid = tid >> 5, lane = tid & 31;
    const int warp_m = wid >> 1;
    const int warp_n = wid & 1;
    const int m0 = blockIdx.y * 128;
    const int n0 = blockIdx.x * 128;

    if (tid == 0) {
        MBAR_INIT(mb0, 1);
        MBAR_INIT(mb0 + 8, 1);
    }
    __syncthreads();

    auto issue_stage = [&](int s, int ch) {
        uint32_t mb = mb0 + s * 8;
        uint32_t base = sb + s * PJ_STAGE_B;
        MBAR_EXPECT_TX(mb, PJ_STAGE_B);
        int cx = ch * TM_BK;
        TMA_LOAD_2D(base,             (const void*)&tmAh, cx, m0, mb);
        TMA_LOAD_2D(base + TM_TILE_B, (const void*)&tmBh, cx, n0, mb);
    };

    float acc[2][8][4];
#pragma unroll
    for (int i = 0; i < 2; i++)
#pragma unroll
        for (int j = 0; j < 8; j++)
#pragma unroll
            for (int q = 0; q < 4; q++) acc[i][j][q] = 0.f;

    const int lrow = lane & 15;
    const int lcol = (lane >> 4) << 3;

    auto compute_stage = [&](int s) {
        uint32_t base = sb + s * PJ_STAGE_B;
        uint32_t sAh = base, sBh = base + TM_TILE_B;
#pragma unroll
        for (int ks = 0; ks < 4; ks++) {
            const int kb = (ks * 16 + lcol) * 2;
            uint32_t ahf[2][4];
#pragma unroll
            for (int mi = 0; mi < 2; mi++) {
                int r = warp_m * 32 + mi * 16 + lrow;
                uint32_t off = SWZ128((uint32_t)(r * 128 + kb));
                ldm_x4(ahf[mi][0], ahf[mi][1], ahf[mi][2], ahf[mi][3], sAh + off);
            }
            uint32_t bf[4][4];
#pragma unroll
            for (int nt = 0; nt < 4; nt++) {
                int r = warp_n * 64 + nt * 16 + lrow;
                uint32_t off = SWZ128((uint32_t)(r * 128 + kb));
                ldm_x4(bf[nt][0], bf[nt][1], bf[nt][2], bf[nt][3], sBh + off);
            }
#pragma unroll
            for (int nt = 0; nt < 4; nt++)
#pragma unroll
                for (int mi = 0; mi < 2; mi++) {
                    mma_f16(acc[mi][nt * 2],     ahf[mi][0], ahf[mi][1], ahf[mi][2], ahf[mi][3],
                            bf[nt][0], bf[nt][2]);
                    mma_f16(acc[mi][nt * 2 + 1], ahf[mi][0], ahf[mi][1], ahf[mi][2], ahf[mi][3],
                            bf[nt][1], bf[nt][3]);
                }
        }
    };

    const int nch = K / TM_BK;
    if (tid == 0) {
        issue_stage(0, 0);
        issue_stage(1, 1);
    }
    int phase[TM_NSTG] = {0, 0};
    for (int ch = 0; ch < nch; ch++) {
        const int s = ch & 1;
        MBAR_WAIT(mb0 + s * 8, phase[s]);
        phase[s] ^= 1;
        compute_stage(s);
        __syncthreads();
        if (ch + 2 < nch && tid == 0) issue_stage(s, ch + 2);
    }

    const int gid = lane >> 2;
    const int tig = lane & 3;
#pragma unroll
    for (int mi = 0; mi < 2; mi++) {
        int rbase = m0 + warp_m * 32 + mi * 16 + gid;
#pragma unroll
        for (int ni = 0; ni < 8; ni++) {
            int col = n0 + warp_n * 64 + ni * 8 + tig * 2;
            float* p0 = Cm + (size_t)rbase * N + col;
            float* p1 = Cm + (size_t)(rbase + 8) * N + col;
            p0[0] = acc[mi][ni][0]; p0[1] = acc[mi][ni][1];
            p1[0] = acc[mi][ni][2]; p1[1] = acc[mi][ni][3];
        }
    }
}

// ---------------------------------------------------------------------------
// fp16 2-term flash attention, TMA-fed (round 15 known-good; al writes removed)
// ---------------------------------------------------------------------------
#define AQ_TILE 16384
#define AKV_TILE 8192
#define AKV_STG (2 * AKV_TILE)
#define AT_NSTG 3
#define SMEM_ATTN (2 * AQ_TILE + AT_NSTG * AKV_STG + 1024)   // 82944

__global__ __launch_bounds__(256, 1) void attn_mma_kernel(
    const __grid_constant__ CUtensorMap tmQh,
    const __grid_constant__ CUtensorMap tmQl,
    const __grid_constant__ CUtensorMap tmKV,
    __half* __restrict__ ah)
{
    extern __shared__ char smem_raw[];
    __shared__ uint64_t mbar_s[1 + AT_NSTG];
    const uint32_t sb = (smem_u32(smem_raw) + 1023u) & ~1023u;
    const uint32_t mbQ = smem_u32(&mbar_s[0]);
    const uint32_t mbKV = mbQ + 8;
    const int tid = threadIdx.x;
    const int wid = tid >> 5, lane = tid & 31;
    const int qt = (int)gridDim.x - 1 - (int)blockIdx.x;
    const int bh = blockIdx.y;
    const int b = bh >> 4, h = bh & 15;
    const int q0 = qt * 128;

    const uint32_t sQh = sb, sQl = sb + AQ_TILE;
    const uint32_t stg0 = sb + 2 * AQ_TILE;
    const int niters = 2 * qt + 2;

    if (tid == 0) {
        MBAR_INIT(mbQ, 1);
#pragma unroll
        for (int s = 0; s < AT_NSTG; s++) MBAR_INIT(mbKV + s * 8, 1);
    }
    __syncthreads();

    auto issue_kv = [&](int s, int it) {
        uint32_t mb = mbKV + s * 8;
        uint32_t base = stg0 + s * AKV_STG;
        MBAR_EXPECT_TX(mb, AKV_STG);
        int cy = b * T_ + it * 64;
        TMA_LOAD_2D(base,            (const void*)&tmKV, C_ + h * HD_,     cy, mb);
        TMA_LOAD_2D(base + AKV_TILE, (const void*)&tmKV, 2 * C_ + h * HD_, cy, mb);
    };

    if (tid == 0) {
        MBAR_EXPECT_TX(mbQ, 2 * AQ_TILE);
        TMA_LOAD_2D(sQh, (const void*)&tmQh, h * HD_, b * T_ + q0, mbQ);
        TMA_LOAD_2D(sQl, (const void*)&tmQl, h * HD_, b * T_ + q0, mbQ);
        issue_kv(0, 0);
        issue_kv(1, 1);
    }

    const int lrow = lane & 15;
    const int lcol = (lane >> 4) << 3;
    const int gid = lane >> 2;
    const int tig = lane & 3;

    MBAR_WAIT(mbQ, 0);

    uint32_t qh[4][4], ql[4][4];
#pragma unroll
    for (int kt = 0; kt < 4; kt++) {
        uint32_t off = SWZ128((uint32_t)((wid * 16 + lrow) * 128 + (kt * 16 + lcol) * 2));
        ldm_x4(qh[kt][0], qh[kt][1], qh[kt][2], qh[kt][3], sQh + off);
        ldm_x4(ql[kt][0], ql[kt][1], ql[kt][2], ql[kt][3], sQl + off);
    }

    float o[8][4];
#pragma unroll
    for (int i = 0; i < 8; i++)
#pragma unroll
        for (int j = 0; j < 4; j++) o[i][j] = 0.f;
    float m0r = -1e30f, m1r = -1e30f, l0r = 0.f, l1r = 0.f;

    for (int it = 0; it < niters; it++) {
        const int s = it % AT_NSTG;
        MBAR_WAIT(mbKV + s * 8, (it / AT_NSTG) & 1);

        const uint32_t sKh = stg0 + s * AKV_STG;
        const uint32_t sVh = sKh + AKV_TILE;
        const int k0 = it * 64;
        const bool active = (q0 + wid * 16 + 15 >= k0);

        if (active) {
            float s4[8][4];
#pragma unroll
            for (int i = 0; i < 8; i++)
#pragma unroll
                for (int j = 0; j < 4; j++) s4[i][j] = 0.f;

#pragma unroll
            for (int kt = 0; kt < 4; kt++) {
                uint32_t kf[4][4];
#pragma unroll
                for (int np = 0; np < 4; np++) {
                    uint32_t boff = SWZ128((uint32_t)((np * 16 + lrow) * 128 + (kt * 16 + lcol) * 2));
                    ldm_x4(kf[np][0], kf[np][1], kf[np][2], kf[np][3], sKh + boff);
                }
#pragma unroll
                for (int np = 0; np < 4; np++) {
                    mma_f16(s4[np * 2],     qh[kt][0], qh[kt][1], qh[kt][2], qh[kt][3],
                            kf[np][0], kf[np][2]);
                    mma_f16(s4[np * 2 + 1], qh[kt][0], qh[kt][1], qh[kt][2], qh[kt][3],
                            kf[np][1], kf[np][3]);
                }
#pragma unroll
                for (int np = 0; np < 4; np++) {
                    mma_f16(s4[np * 2],     ql[kt][0], ql[kt][1], ql[kt][2], ql[kt][3],
                            kf[np][0], kf[np][2]);
                    mma_f16(s4[np * 2 + 1], ql[kt][0], ql[kt][1], ql[kt][2], ql[kt][3],
                            kf[np][1], kf[np][3]);
                }
            }

#pragma unroll
            for (int ni = 0; ni < 8; ni++)
#pragma unroll
                for (int e = 0; e < 4; e++) s4[ni][e] *= 0.125f;
            if (it == 0 && tig == 0) { s4[0][0] += 1.0f; s4[0][2] += 1.0f; }
            const int grow0 = q0 + wid * 16 + gid;
            const int grow1 = grow0 + 8;
            if (k0 + 63 > q0 + wid * 16) {
#pragma unroll
                for (int ni = 0; ni < 8; ni++) {
                    int gc = k0 + ni * 8 + tig * 2;
                    if (gc > grow0)     s4[ni][0] = -1e30f;
                    if (gc + 1 > grow0) s4[ni][1] = -1e30f;
                    if (gc > grow1)     s4[ni][2] = -1e30f;
                    if (gc + 1 > grow1) s4[ni][3] = -1e30f;
                }
            }

            float mx0 = s4[0][0], mx1 = s4[0][2];
#pragma unroll
            for (int ni = 0; ni < 8; ni++) {
                mx0 = fmaxf(mx0, fmaxf(s4[ni][0], s4[ni][1]));
                mx1 = fmaxf(mx1, fmaxf(s4[ni][2], s4[ni][3]));
            }
            mx0 = fmaxf(mx0, __shfl_xor_sync(0xffffffffu, mx0, 1));
            mx0 = fmaxf(mx0, __shfl_xor_sync(0xffffffffu, mx0, 2));
            mx1 = fmaxf(mx1, __shfl_xor_sync(0xffffffffu, mx1, 1));
            mx1 = fmaxf(mx1, __shfl_xor_sync(0xffffffffu, mx1, 2));
            float mn0 = fmaxf(m0r, mx0), mn1 = fmaxf(m1r, mx1);
            float a0 = __expf(m0r - mn0), a1 = __expf(m1r - mn1);
            m0r = mn0; m1r = mn1;
            float sum0 = 0.f, sum1 = 0.f;
#pragma unroll
            for (int ni = 0; ni < 8; ni++) {
                s4[ni][0] = __expf(s4[ni][0] - mn0);
                s4[ni][1] = __expf(s4[ni][1] - mn0);
                s4[ni][2] = __expf(s4[ni][2] - mn1);
                s4[ni][3] = __expf(s4[ni][3] - mn1);
                sum0 += s4[ni][0] + s4[ni][1];
                sum1 += s4[ni][2] + s4[ni][3];
            }
            sum0 += __shfl_xor_sync(0xffffffffu, sum0, 1);
            sum0 += __shfl_xor_sync(0xffffffffu, sum0, 2);
            sum1 += __shfl_xor_sync(0xffffffffu, sum1, 1);
            sum1 += __shfl_xor_sync(0xffffffffu, sum1, 2);
            l0r = l0r * a0 + sum0;
            l1r = l1r * a1 + sum1;

#pragma unroll
            for (int ni = 0; ni < 8; ni++) {
                o[ni][0] *= a0; o[ni][1] *= a0;
                o[ni][2] *= a1; o[ni][3] *= a1;
            }

#pragma unroll
            for (int kt = 0; kt < 4; kt++) {
                uint32_t ph[4], pl[4];
                {
                    float v0 = s4[2 * kt][0], v1 = s4[2 * kt][1];
                    float v2 = s4[2 * kt][2], v3 = s4[2 * kt][3];
                    float w0 = s4[2 * kt + 1][0], w1 = s4[2 * kt + 1][1];
                    float w2 = s4[2 * kt + 1][2], w3 = s4[2 * kt + 1][3];
                    ph[0] = pack_f16(v0, v1); ph[1] = pack_f16(v2, v3);
                    ph[2] = pack_f16(w0, w1); ph[3] = pack_f16(w2, w3);
                    pl[0] = pack_f16(f16_residual(v0), f16_residual(v1));
                    pl[1] = pack_f16(f16_residual(v2), f16_residual(v3));
                    pl[2] = pack_f16(f16_residual(w0), f16_residual(w1));
                    pl[3] = pack_f16(f16_residual(w2), f16_residual(w3));
                }
                uint32_t vf[4][4];
#pragma unroll
                for (int dp = 0; dp < 4; dp++) {
                    uint32_t voff = SWZ128((uint32_t)((kt * 16 + lrow) * 128 + (dp * 16 + lcol) * 2));
                    ldm_x4_t(vf[dp][0], vf[dp][1], vf[dp][2], vf[dp][3], sVh + voff);
                }
#pragma unroll
                for (int dp = 0; dp < 4; dp++) {
                    mma_f16(o[dp * 2],     ph[0], ph[1], ph[2], ph[3], vf[dp][0], vf[dp][1]);
                    mma_f16(o[dp * 2 + 1], ph[0], ph[1], ph[2], ph[3], vf[dp][2], vf[dp][3]);
                }
#pragma unroll
                for (int dp = 0; dp < 4; dp++) {
                    mma_f16(o[dp * 2],     pl[0], pl[1], pl[2], pl[3], vf[dp][0], vf[dp][1]);
                    mma_f16(o[dp * 2 + 1], pl[0], pl[1], pl[2], pl[3], vf[dp][2], vf[dp][3]);
                }
            }
        }

        __syncthreads();
        if (it + 2 < niters && tid == 0) issue_kv((it + 2) % AT_NSTG, it + 2);
    }

    // ---- epilogue: hi only (proj GEMM is 1-term) ----
    const float inv0 = 1.f / l0r, inv1 = 1.f / l1r;
    const int grow0 = q0 + wid * 16 + gid;
    const size_t r0o = (size_t)(b * T_ + grow0) * C_;
    const size_t r1o = (size_t)(b * T_ + grow0 + 8) * C_;
#pragma unroll
    for (int ni = 0; ni < 8; ni++) {
        int col = h * HD_ + ni * 8 + tig * 2;
        *(uint32_t*)(ah + r0o + col) = pack_f16(o[ni][0] * inv0, o[ni][1] * inv0);
        *(uint32_t*)(ah + r1o + col) = pack_f16(o[ni][2] * inv1, o[ni][3] * inv1);
    }
}

// ---------------------------------------------------------------------------
// Host: tensormap construction via driver entry point
// ---------------------------------------------------------------------------
typedef CUresult (*EncodeTiledFn)(
    CUtensorMap*, CUtensorMapDataType, cuuint32_t, void*,
    const cuuint64_t*, const cuuint64_t*, const cuuint32_t*, const cuuint32_t*,
    CUtensorMapInterleave, CUtensorMapSwizzle, CUtensorMapL2promotion,
    CUtensorMapFloatOOBfill);

static void make_map2d(EncodeTiledFn fn, CUtensorMap* m, void* base, int rows, int cols,
                       int boxy) {
    cuuint64_t dims[2]    = {(cuuint64_t)cols, (cuuint64_t)rows};
    cuuint64_t strides[1] = {(cuuint64_t)cols * 2};
    cuuint32_t box[2]     = {64, (cuuint32_t)boxy};
    cuuint32_t estr[2]    = {1, 1};
    fn(m, CU_TENSOR_MAP_DATA_TYPE_FLOAT16, 2, base, dims, strides, box, estr,
       CU_TENSOR_MAP_INTERLEAVE_NONE, CU_TENSOR_MAP_SWIZZLE_128B,
       CU_TENSOR_MAP_L2_PROMOTION_L2_128B, CU_TENSOR_MAP_FLOAT_OOB_FILL_NONE);
}

extern "C" void kernel_launch(void* const* d_in, const int* in_sizes, int n_in,
                              void* d_out, int out_size)
{
    const float* x  = (const float*)d_in[0];
    const float* Wa = (const float*)d_in[1];
    const float* Wp = (const float*)d_in[2];
    float* y = (float*)d_out;

    __half *qkvh, *qkvl, *xh, *xl, *wah, *wph, *ah;
    cudaGetSymbolAddress((void**)&qkvh, g_qkvh);
    cudaGetSymbolAddress((void**)&qkvl, g_qkvl);
    cudaGetSymbolAddress((void**)&xh, g_xh);
    cudaGetSymbolAddress((void**)&xl, g_xl);
    cudaGetSymbolAddress((void**)&wah, g_wah);
    cudaGetSymbolAddress((void**)&wph, g_wph);
    cudaGetSymbolAddress((void**)&ah, g_ah);

    EncodeTiledFn enc = nullptr;
    cudaDriverEntryPointQueryResult qr;
#if CUDART_VERSION >= 12050
    cudaGetDriverEntryPointByVersion("cuTensorMapEncodeTiled", (void**)&enc, 12000,
                                     cudaEnableDefault, &qr);
#else
    cudaGetDriverEntryPoint("cuTensorMapEncodeTiled", (void**)&enc,
                            cudaEnableDefault, &qr);
#endif

    CUtensorMap m_xh, m_xl, m_wa, m_ah, m_wp, m_qh, m_ql, m_kv;
    make_map2d(enc, &m_xh, xh,  M_ROWS, C_, 128);
    make_map2d(enc, &m_xl, xl,  M_ROWS, C_, 128);
    make_map2d(enc, &m_wa, wah, C3_,    C_, 128);
    make_map2d(enc, &m_ah, ah,  M_ROWS, C_, 128);
    make_map2d(enc, &m_wp, wph, C_,     C_, 128);
    make_map2d(enc, &m_qh, qkvh, M_ROWS, C3_, 128);
    make_map2d(enc, &m_ql, qkvl, M_ROWS, C3_, 128);
    make_map2d(enc, &m_kv, qkvh, M_ROWS, C3_, 64);

    cudaFuncSetAttribute(gemm_qkv_kernel,
                         cudaFuncAttributeMaxDynamicSharedMemorySize, SMEM_QKV);
    cudaFuncSetAttribute(gemm_proj_kernel,
                         cudaFuncAttributeMaxDynamicSharedMemorySize, SMEM_PROJ);
    cudaFuncSetAttribute(attn_mma_kernel,
                         cudaFuncAttributeMaxDynamicSharedMemorySize, SMEM_ATTN);

    // 1) splits / weight transposes
    {
        int n4 = M_ROWS * C_ / 4;
        split_kernel<<<(n4 + 255) / 256, 256>>>(x, xh, xl, n4);
        dim3 grid_a(C3_ / 32, C_ / 32);
        transpose_f16_kernel<<<grid_a, dim3(32, 8)>>>(Wa, wah, C_, C3_);
        dim3 grid_p(C_ / 32, C_ / 32);
        transpose_f16_kernel<<<grid_p, dim3(32, 8)>>>(Wp, wph, C_, C_);
    }

    // 2) merged QKV GEMM (Q: 2-term hi/lo; KV: 1-term hi)
    {
        dim3 grid(C3_ / 128, M_ROWS / 128);
        gemm_qkv_kernel<<<grid, 256, SMEM_QKV>>>(
            m_xh, m_xl, m_wa, qkvh, qkvl, M_ROWS, C3_, C_);
    }

    // 3) flash attention (TMA-fed) -> fp16 hi only
    {
        dim3 grid(T_ / 128, B_ * H_);
        attn_mma_kernel<<<grid, 256, SMEM_ATTN>>>(m_qh, m_ql, m_kv, ah);
    }

    // 4) y = ah @ W_proj (1-term, fp32 out)
    {
        dim3 grid(C_ / 128, M_ROWS / 128);
        gemm_proj_kernel<<<grid, 256, SMEM_PROJ>>>(m_ah, m_wp, y, M_ROWS, C_, C_);
    }
}